// round 6
// baseline (speedup 1.0000x reference)
#include <cuda_runtime.h>

#define NN  100000
#define EE  1600000
#define PP  800000
#define HEN 20000
#define FIN 128
#define D   64
#define NC  40

typedef unsigned long long u64;

// ---------------- scratch (device globals; no allocation allowed) ----------------
__device__ float g_xw [NN * D];
__device__ float g_h1 [NN * D];
__device__ float g_h2 [NN * D];
__device__ float g_xg [NN * D];
__device__ float g_t40[NN * NC];
__device__ float g_ef [HEN * D];
__device__ float g_dis  [NN];
__device__ float g_Dninv[NN];
__device__ float g_Binv [HEN];
__device__ int g_cntE[NN], g_cntH[HEN], g_cntN[NN];
__device__ int g_offE[NN + 1], g_offH[HEN + 1], g_offN[NN + 1];
__device__ int g_curE[NN], g_curH[HEN], g_curN[NN];
__device__ int g_csrE[EE];
__device__ int g_csrHn[PP];
__device__ int g_csrNh[PP];
__device__ int g_bsum[512];
__device__ int g_me, g_mh;

// ---------------- helpers ----------------
__device__ __forceinline__ long long ldidx(const void* b, long long i, int m64) {
    return m64 ? ((const long long*)b)[i] : (long long)((const int*)b)[i];
}
__device__ __forceinline__ u64 fma2(u64 a, u64 b, u64 c) {
    u64 d;
    asm("fma.rn.f32x2 %0, %1, %2, %3;" : "=l"(d) : "l"(a), "l"(b), "l"(c));
    return d;
}
__device__ __forceinline__ float unpack_sum(u64 v) {
    float lo, hi;
    asm("mov.b64 {%0, %1}, %2;" : "=f"(lo), "=f"(hi) : "l"(v));
    return lo + hi;
}
__device__ __forceinline__ u64 packf2(float lo, float hi) {
    u64 p;
    asm("mov.b64 %0, {%1, %2};" : "=l"(p) : "f"(lo), "f"(hi));
    return p;
}

// ---------------- dtype detection ----------------
__global__ void k_detect(const int* e32, const int* h32) {
    int nze = 0, nzh = 0;
    for (int i = threadIdx.x; i < 4096; i += blockDim.x) {
        if (e32[2 * i + 1] != 0) nze = 1;
        if (h32[2 * i + 1] != 0) nzh = 1;
    }
    nze = __syncthreads_or(nze);
    nzh = __syncthreads_or(nzh);
    if (threadIdx.x == 0) { g_me = nze ? 0 : 1; g_mh = nzh ? 0 : 1; }
}

__global__ void k_zero_cnt() {
    int i = blockIdx.x * blockDim.x + threadIdx.x;
    if (i < NN) { g_cntE[i] = 0; g_cntN[i] = 0; }
    if (i < HEN) g_cntH[i] = 0;
}

// ---------------- fused counting ----------------
__global__ void k_cnt(const void* eidx, const void* hidx) {
    int i = blockIdx.x * blockDim.x + threadIdx.x;
    if (i < EE) {
        int dst = (int)ldidx(eidx, (long long)EE + i, g_me);
        atomicAdd(&g_cntE[dst], 1);
    }
    if (i < PP) {
        int m = g_mh;
        int node = (int)ldidx(hidx, i, m);
        int he   = (int)ldidx(hidx, (long long)PP + i, m);
        atomicAdd(&g_cntN[node], 1);
        atomicAdd(&g_cntH[he], 1);
    }
}

// ---------------- fused exclusive scans (y selects array) ----------------
__global__ void k_scan1f() {
    const int* cnt; int n; int* excl; int* bs;
    if (blockIdx.y == 0)      { cnt = g_cntE; n = NN;  excl = g_offE; bs = g_bsum;       }
    else if (blockIdx.y == 1) { cnt = g_cntN; n = NN;  excl = g_offN; bs = g_bsum + 128; }
    else                      { cnt = g_cntH; n = HEN; excl = g_offH; bs = g_bsum + 256; }
    __shared__ int wsum[8];
    int t = threadIdx.x;
    int base = blockIdx.x * 1024 + t * 4;
    int v0 = 0, v1 = 0, v2 = 0, v3 = 0;
    if (base + 0 < n) v0 = cnt[base + 0];
    if (base + 1 < n) v1 = cnt[base + 1];
    if (base + 2 < n) v2 = cnt[base + 2];
    if (base + 3 < n) v3 = cnt[base + 3];
    int tot = v0 + v1 + v2 + v3;
    int lane = t & 31, w = t >> 5;
    int p = tot;
    for (int d = 1; d < 32; d <<= 1) { int u = __shfl_up_sync(~0u, p, d); if (lane >= d) p += u; }
    if (lane == 31) wsum[w] = p;
    __syncthreads();
    int wb = 0;
    for (int i = 0; i < w; i++) wb += wsum[i];
    int e0 = wb + p - tot;
    if (base + 0 < n) excl[base + 0] = e0;
    if (base + 1 < n) excl[base + 1] = e0 + v0;
    if (base + 2 < n) excl[base + 2] = e0 + v0 + v1;
    if (base + 3 < n) excl[base + 3] = e0 + v0 + v1 + v2;
    if (t == 255) bs[blockIdx.x] = wb + p;
}
__global__ void k_scan2f() {
    int y = blockIdx.x;
    int nb = (y == 2) ? (HEN + 1023) / 1024 : (NN + 1023) / 1024;
    int* b = g_bsum + y * 128;
    int t = threadIdx.x;       // 1024
    int v = (t < nb) ? b[t] : 0;
    int lane = t & 31, w = t >> 5;
    int p = v;
    for (int d = 1; d < 32; d <<= 1) { int u = __shfl_up_sync(~0u, p, d); if (lane >= d) p += u; }
    __shared__ int ws[32];
    if (lane == 31) ws[w] = p;
    __syncthreads();
    if (t < 32) {
        int q = ws[t], pp = q;
        for (int d = 1; d < 32; d <<= 1) { int u = __shfl_up_sync(~0u, pp, d); if (t >= d) pp += u; }
        ws[t] = pp - q;
    }
    __syncthreads();
    if (t < nb) b[t] = ws[w] + p - v;
}
__global__ void k_scan3f() {  // offsets += block base; init cursors; fold norms in y==0
    int i = blockIdx.x * blockDim.x + threadIdx.x;
    int y = blockIdx.y;
    if (y == 0) {
        if (i < NN) {
            int v = g_offE[i] + g_bsum[i >> 10];
            g_offE[i] = v; g_curE[i] = v;
            g_dis[i] = rsqrtf((float)g_cntE[i] + 1.0f);
            int dn = g_cntN[i];
            g_Dninv[i] = dn > 0 ? 1.0f / (float)dn : 0.0f;
        }
        if (i < HEN) {
            int bh = g_cntH[i];
            g_Binv[i] = bh > 0 ? 1.0f / (float)bh : 0.0f;
        }
        if (i == 0) g_offE[NN] = EE;
    } else if (y == 1) {
        if (i < NN) {
            int v = g_offN[i] + g_bsum[128 + (i >> 10)];
            g_offN[i] = v; g_curN[i] = v;
        }
        if (i == 0) g_offN[NN] = PP;
    } else {
        if (i < HEN) {
            int v = g_offH[i] + g_bsum[256 + (i >> 10)];
            g_offH[i] = v; g_curH[i] = v;
        }
        if (i == 0) g_offH[HEN] = PP;
    }
}

// ---------------- fused CSR fill ----------------
__global__ void k_fill(const void* eidx, const void* hidx) {
    int i = blockIdx.x * blockDim.x + threadIdx.x;
    if (i < EE) {
        int m = g_me;
        int src = (int)ldidx(eidx, i, m);
        int dst = (int)ldidx(eidx, (long long)EE + i, m);
        int pos = atomicAdd(&g_curE[dst], 1);
        g_csrE[pos] = src;
    }
    if (i < PP) {
        int m = g_mh;
        int node = (int)ldidx(hidx, i, m);
        int he   = (int)ldidx(hidx, (long long)PP + i, m);
        int p1 = atomicAdd(&g_curH[he], 1);   g_csrHn[p1] = node;
        int p2 = atomicAdd(&g_curN[node], 1); g_csrNh[p2] = he;
    }
}

// ---------------- f32x2-packed GEMM: out = rowscale * ([A1|A2] @ W) + bias ----------------
// Even/odd-K partial sums live in the lo/hi halves of each f32x2 accumulator.
template<int K1, int K2, int C>
__global__ void k_gemm(const float* __restrict__ A1, const float* __restrict__ A2,
                       const float* __restrict__ W, float* __restrict__ out,
                       const float* __restrict__ rowscale, const float* __restrict__ bias) {
    constexpr int KT = K1 + K2;
    constexpr int CG = C / 4;
    constexpr int NTH = CG * 16;
    __shared__ u64 Ws[(KT / 2) * C];   // Ws[kp*C + c] = {W[2kp][c], W[2kp+1][c]}
    int tid = threadIdx.x;
    for (int i = tid; i < (KT / 2) * C; i += NTH) {
        int kp = i / C, c = i - kp * C;
        Ws[i] = packf2(W[(2 * kp) * C + c], W[(2 * kp + 1) * C + c]);
    }
    __syncthreads();
    int cg = tid % CG, rg = tid / CG;
    int row0 = blockIdx.x * 64 + rg * 4;
    int r[4];
    #pragma unroll
    for (int j = 0; j < 4; j++) { int rr = row0 + j; r[j] = rr < NN ? rr : NN - 1; }

    u64 acc[4][4] = {};
    #pragma unroll 2
    for (int k = 0; k < K1; k += 4) {
        ulonglong2 a[4];
        #pragma unroll
        for (int j = 0; j < 4; j++)
            a[j] = *(const ulonglong2*)(A1 + (size_t)r[j] * K1 + k);
        #pragma unroll
        for (int kp = 0; kp < 2; kp++) {
            ulonglong2 w01 = *(const ulonglong2*)&Ws[(k / 2 + kp) * C + cg * 4];
            ulonglong2 w23 = *(const ulonglong2*)&Ws[(k / 2 + kp) * C + cg * 4 + 2];
            #pragma unroll
            for (int j = 0; j < 4; j++) {
                u64 av = kp ? a[j].y : a[j].x;
                acc[j][0] = fma2(av, w01.x, acc[j][0]);
                acc[j][1] = fma2(av, w01.y, acc[j][1]);
                acc[j][2] = fma2(av, w23.x, acc[j][2]);
                acc[j][3] = fma2(av, w23.y, acc[j][3]);
            }
        }
    }
    if (K2 > 0) {
        #pragma unroll 2
        for (int k = 0; k < K2; k += 4) {
            ulonglong2 a[4];
            #pragma unroll
            for (int j = 0; j < 4; j++)
                a[j] = *(const ulonglong2*)(A2 + (size_t)r[j] * K2 + k);
            #pragma unroll
            for (int kp = 0; kp < 2; kp++) {
                ulonglong2 w01 = *(const ulonglong2*)&Ws[((K1 + k) / 2 + kp) * C + cg * 4];
                ulonglong2 w23 = *(const ulonglong2*)&Ws[((K1 + k) / 2 + kp) * C + cg * 4 + 2];
                #pragma unroll
                for (int j = 0; j < 4; j++) {
                    u64 av = kp ? a[j].y : a[j].x;
                    acc[j][0] = fma2(av, w01.x, acc[j][0]);
                    acc[j][1] = fma2(av, w01.y, acc[j][1]);
                    acc[j][2] = fma2(av, w23.x, acc[j][2]);
                    acc[j][3] = fma2(av, w23.y, acc[j][3]);
                }
            }
        }
    }
    #pragma unroll
    for (int j = 0; j < 4; j++) {
        int rr = row0 + j;
        if (rr >= NN) break;
        float s = rowscale ? rowscale[rr] : 1.0f;
        float4 o;
        o.x = unpack_sum(acc[j][0]) * s;
        o.y = unpack_sum(acc[j][1]) * s;
        o.z = unpack_sum(acc[j][2]) * s;
        o.w = unpack_sum(acc[j][3]) * s;
        if (bias) {
            const float4 bb = *(const float4*)(bias + cg * 4);
            o.x += bb.x; o.y += bb.y; o.z += bb.z; o.w += bb.w;
        }
        *(float4*)(out + (size_t)rr * C + cg * 4) = o;
    }
}

// ---------------- gathers (CSR, register accumulate, fused epilogues) ----------------
#define ACC4(acc, v) { acc.x += v.x; acc.y += v.y; acc.z += v.z; acc.w += v.w; }

__global__ void k_gath_he(const float* __restrict__ xw) {
    int t = blockIdx.x * blockDim.x + threadIdx.x;
    int he = t >> 4, l = t & 15;
    if (he >= HEN) return;
    int s = g_offH[he], e = g_offH[he + 1];
    float4 acc = make_float4(0.f, 0.f, 0.f, 0.f);
    int i = s;
    for (; i + 3 < e; i += 4) {
        int n0 = g_csrHn[i], n1 = g_csrHn[i + 1], n2 = g_csrHn[i + 2], n3 = g_csrHn[i + 3];
        float4 v0 = *(const float4*)(xw + (size_t)n0 * D + l * 4);
        float4 v1 = *(const float4*)(xw + (size_t)n1 * D + l * 4);
        float4 v2 = *(const float4*)(xw + (size_t)n2 * D + l * 4);
        float4 v3 = *(const float4*)(xw + (size_t)n3 * D + l * 4);
        ACC4(acc, v0); ACC4(acc, v1); ACC4(acc, v2); ACC4(acc, v3);
    }
    for (; i < e; i++) {
        int n0 = g_csrHn[i];
        float4 v0 = *(const float4*)(xw + (size_t)n0 * D + l * 4);
        ACC4(acc, v0);
    }
    float b = g_Binv[he];
    acc.x *= b; acc.y *= b; acc.z *= b; acc.w *= b;
    *(float4*)(g_ef + (size_t)he * D + l * 4) = acc;
}

__global__ void k_gath_e2n(const float* __restrict__ bias, float* __restrict__ out, int relu) {
    int t = blockIdx.x * blockDim.x + threadIdx.x;
    int node = t >> 4, l = t & 15;
    if (node >= NN) return;
    int s = g_offN[node], e = g_offN[node + 1];
    float4 acc = make_float4(0.f, 0.f, 0.f, 0.f);
    int i = s;
    for (; i + 3 < e; i += 4) {
        int h0 = g_csrNh[i], h1 = g_csrNh[i + 1], h2 = g_csrNh[i + 2], h3 = g_csrNh[i + 3];
        float4 v0 = *(const float4*)(g_ef + (size_t)h0 * D + l * 4);
        float4 v1 = *(const float4*)(g_ef + (size_t)h1 * D + l * 4);
        float4 v2 = *(const float4*)(g_ef + (size_t)h2 * D + l * 4);
        float4 v3 = *(const float4*)(g_ef + (size_t)h3 * D + l * 4);
        ACC4(acc, v0); ACC4(acc, v1); ACC4(acc, v2); ACC4(acc, v3);
    }
    for (; i < e; i++) {
        int h0 = g_csrNh[i];
        float4 v0 = *(const float4*)(g_ef + (size_t)h0 * D + l * 4);
        ACC4(acc, v0);
    }
    float dv = g_Dninv[node];
    float4 bb = *(const float4*)(bias + l * 4);
    float4 o;
    o.x = dv * acc.x + bb.x; o.y = dv * acc.y + bb.y;
    o.z = dv * acc.z + bb.z; o.w = dv * acc.w + bb.w;
    if (relu) {
        o.x = fmaxf(o.x, 0.f); o.y = fmaxf(o.y, 0.f);
        o.z = fmaxf(o.z, 0.f); o.w = fmaxf(o.w, 0.f);
    }
    *(float4*)(out + (size_t)node * D + l * 4) = o;
}

__global__ void k_gcn64(const float* __restrict__ xwd, const float* __restrict__ bias,
                        float* __restrict__ out) {
    int t = blockIdx.x * blockDim.x + threadIdx.x;
    int node = t >> 4, l = t & 15;
    if (node >= NN) return;
    int s = g_offE[node], e = g_offE[node + 1];
    float4 acc = make_float4(0.f, 0.f, 0.f, 0.f);
    int i = s;
    for (; i + 3 < e; i += 4) {
        int s0 = g_csrE[i], s1 = g_csrE[i + 1], s2 = g_csrE[i + 2], s3 = g_csrE[i + 3];
        float4 v0 = *(const float4*)(xwd + (size_t)s0 * D + l * 4);
        float4 v1 = *(const float4*)(xwd + (size_t)s1 * D + l * 4);
        float4 v2 = *(const float4*)(xwd + (size_t)s2 * D + l * 4);
        float4 v3 = *(const float4*)(xwd + (size_t)s3 * D + l * 4);
        ACC4(acc, v0); ACC4(acc, v1); ACC4(acc, v2); ACC4(acc, v3);
    }
    for (; i < e; i++) {
        int s0 = g_csrE[i];
        float4 v0 = *(const float4*)(xwd + (size_t)s0 * D + l * 4);
        ACC4(acc, v0);
    }
    float4 self = *(const float4*)(xwd + (size_t)node * D + l * 4);
    float ds = g_dis[node];
    float4 bb = *(const float4*)(bias + l * 4);
    float4 o;
    o.x = fmaxf(ds * (acc.x + self.x) + bb.x, 0.f);
    o.y = fmaxf(ds * (acc.y + self.y) + bb.y, 0.f);
    o.z = fmaxf(ds * (acc.z + self.z) + bb.z, 0.f);
    o.w = fmaxf(ds * (acc.w + self.w) + bb.w, 0.f);
    *(float4*)(out + (size_t)node * D + l * 4) = o;
}

__global__ void k_gcn40(const float* __restrict__ bias, float* __restrict__ out) {
    int t = blockIdx.x * blockDim.x + threadIdx.x;   // 10 lanes per node
    int node = t / 10, l = t % 10;
    if (node >= NN) return;
    int s = g_offE[node], e = g_offE[node + 1];
    float4 acc = make_float4(0.f, 0.f, 0.f, 0.f);
    int i = s;
    for (; i + 3 < e; i += 4) {
        int s0 = g_csrE[i], s1 = g_csrE[i + 1], s2 = g_csrE[i + 2], s3 = g_csrE[i + 3];
        float4 v0 = *(const float4*)(g_t40 + (size_t)s0 * NC + l * 4);
        float4 v1 = *(const float4*)(g_t40 + (size_t)s1 * NC + l * 4);
        float4 v2 = *(const float4*)(g_t40 + (size_t)s2 * NC + l * 4);
        float4 v3 = *(const float4*)(g_t40 + (size_t)s3 * NC + l * 4);
        ACC4(acc, v0); ACC4(acc, v1); ACC4(acc, v2); ACC4(acc, v3);
    }
    for (; i < e; i++) {
        int s0 = g_csrE[i];
        float4 v0 = *(const float4*)(g_t40 + (size_t)s0 * NC + l * 4);
        ACC4(acc, v0);
    }
    float4 self = *(const float4*)(g_t40 + (size_t)node * NC + l * 4);
    float ds = g_dis[node];
    float4 bb = *(const float4*)(bias + l * 4);
    float4 o;
    o.x = ds * (acc.x + self.x) + bb.x;
    o.y = ds * (acc.y + self.y) + bb.y;
    o.z = ds * (acc.z + self.z) + bb.z;
    o.w = ds * (acc.w + self.w) + bb.w;
    *(float4*)(out + (size_t)node * NC + l * 4) = o;
}

// ---------------- launch ----------------
extern "C" void kernel_launch(void* const* d_in, const int* in_sizes, int n_in,
                              void* d_out, int out_size) {
    const float* x    = (const float*)d_in[0];
    const void*  eidx = d_in[1];
    const void*  hidx = d_in[2];
    const float* W_h1 = (const float*)d_in[3];
    const float* b_h1 = (const float*)d_in[4];
    const float* W_h2 = (const float*)d_in[5];
    const float* b_h2 = (const float*)d_in[6];
    const float* W_c1 = (const float*)d_in[7];
    const float* b_c1 = (const float*)d_in[8];
    const float* W_c2 = (const float*)d_in[9];
    const float* b_c2 = (const float*)d_in[10];
    const float* W_lp = (const float*)d_in[11];
    const float* b_lp = (const float*)d_in[12];
    float* out = (float*)d_out;

    float *p_xw, *p_h1, *p_h2, *p_xg, *p_t40, *p_dis;
    cudaGetSymbolAddress((void**)&p_xw,  g_xw);
    cudaGetSymbolAddress((void**)&p_h1,  g_h1);
    cudaGetSymbolAddress((void**)&p_h2,  g_h2);
    cudaGetSymbolAddress((void**)&p_xg,  g_xg);
    cudaGetSymbolAddress((void**)&p_t40, g_t40);
    cudaGetSymbolAddress((void**)&p_dis, g_dis);

    const int B = 256;

    k_detect<<<1, 256>>>((const int*)eidx, (const int*)hidx);

    // ---- CSR build (fused) ----
    k_zero_cnt<<<(NN + B - 1) / B, B>>>();
    k_cnt<<<(EE + B - 1) / B, B>>>(eidx, hidx);
    k_scan1f<<<dim3((NN + 1023) / 1024, 3), 256>>>();
    k_scan2f<<<3, 1024>>>();
    k_scan3f<<<dim3((NN + B - 1) / B, 3), B>>>();
    k_fill<<<(EE + B - 1) / B, B>>>(eidx, hidx);

    const int GR = (NN + 63) / 64;

    // ---- hyperconv 1 ----
    k_gemm<FIN, 0, D><<<GR, 256>>>(x, nullptr, W_h1, p_xw, nullptr, nullptr);
    k_gath_he<<<(HEN * 16 + B - 1) / B, B>>>(p_xw);
    k_gath_e2n<<<(NN * 16 + B - 1) / B, B>>>(b_h1, p_h1, 1);

    // ---- hyperconv 2 ----
    k_gemm<D, 0, D><<<GR, 256>>>(p_h1, nullptr, W_h2, p_xw, nullptr, nullptr);
    k_gath_he<<<(HEN * 16 + B - 1) / B, B>>>(p_xw);
    k_gath_e2n<<<(NN * 16 + B - 1) / B, B>>>(b_h2, p_h2, 0);

    // ---- gcn 1 (concat input, dis-prescaled) ----
    k_gemm<FIN, D, D><<<GR, 256>>>(x, p_h2, W_c1, p_xw, p_dis, nullptr);
    k_gcn64<<<(NN * 16 + B - 1) / B, B>>>(p_xw, b_c1, p_xg);

    // ---- gcn 2 + linear head ----
    k_gemm<D, 0, NC><<<GR, 160>>>(p_xg, nullptr, W_c2, p_t40, p_dis, nullptr);
    k_gcn40<<<(NN * 10 + 319) / 320, 320>>>(b_c2, p_xw);
    k_gemm<NC, 0, NC><<<GR, 160>>>(p_xw, nullptr, W_lp, out, nullptr, b_lp);
}

// round 9
// speedup vs baseline: 1.1667x; 1.1667x over previous
#include <cuda_runtime.h>

#define NN  100000
#define EE  1600000
#define PP  800000
#define HEN 20000
#define FIN 128
#define D   64
#define NC  40

// ---------------- scratch (device globals; no allocation allowed) ----------------
__device__ float g_xw [NN * D];
__device__ float g_h1 [NN * D];
__device__ float g_h2 [NN * D];
__device__ float g_xg [NN * D];
__device__ float g_t40[NN * NC];
__device__ float g_ef [HEN * D];
__device__ float g_dis  [NN];
__device__ float g_Dninv[NN];
__device__ float g_Binv [HEN];
__device__ int g_cntE[NN], g_cntH[HEN], g_cntN[NN];   // static zero-init; re-zeroed in k_fill
__device__ int g_offE[NN + 1], g_offH[HEN + 1], g_offN[NN + 1];
__device__ int g_curE[NN], g_curH[HEN], g_curN[NN];
__device__ int g_csrE[EE];
__device__ int g_csrHn[PP];
__device__ int g_csrNh[PP];
__device__ int g_bsum[512];

// ---------------- helpers ----------------
// Per-block dtype sniff: for int64 storage of values < 2^31, every high 32-bit
// word is 0. For int32 storage of random indices, 8 consecutive high words all
// zero has probability ~1e-40. Uniform branch per block.
__device__ __forceinline__ int sniff64(const void* b) {
    int acc = 0;
    #pragma unroll
    for (int i = 0; i < 8; i++) acc |= ((const int*)b)[2 * i + 1];
    return acc == 0;
}
__device__ __forceinline__ long long ldidx(const void* b, long long i, int m64) {
    return m64 ? ((const long long*)b)[i] : (long long)((const int*)b)[i];
}

// ---------------- fused counting ----------------
__global__ void k_cnt(const void* eidx, const void* hidx) {
    int me = sniff64(eidx), mh = sniff64(hidx);
    int i = blockIdx.x * blockDim.x + threadIdx.x;
    if (i < EE) {
        int dst = (int)ldidx(eidx, (long long)EE + i, me);
        atomicAdd(&g_cntE[dst], 1);
    }
    if (i < PP) {
        int node = (int)ldidx(hidx, i, mh);
        int he   = (int)ldidx(hidx, (long long)PP + i, mh);
        atomicAdd(&g_cntN[node], 1);
        atomicAdd(&g_cntH[he], 1);
    }
}

// ---------------- fused exclusive scans (y selects array) ----------------
__global__ void k_scan1f() {
    const int* cnt; int n; int* excl; int* bs;
    if (blockIdx.y == 0)      { cnt = g_cntE; n = NN;  excl = g_offE; bs = g_bsum;       }
    else if (blockIdx.y == 1) { cnt = g_cntN; n = NN;  excl = g_offN; bs = g_bsum + 128; }
    else                      { cnt = g_cntH; n = HEN; excl = g_offH; bs = g_bsum + 256; }
    __shared__ int wsum[8];
    int t = threadIdx.x;
    int base = blockIdx.x * 1024 + t * 4;
    int v0 = 0, v1 = 0, v2 = 0, v3 = 0;
    if (base + 0 < n) v0 = cnt[base + 0];
    if (base + 1 < n) v1 = cnt[base + 1];
    if (base + 2 < n) v2 = cnt[base + 2];
    if (base + 3 < n) v3 = cnt[base + 3];
    int tot = v0 + v1 + v2 + v3;
    int lane = t & 31, w = t >> 5;
    int p = tot;
    for (int d = 1; d < 32; d <<= 1) { int u = __shfl_up_sync(~0u, p, d); if (lane >= d) p += u; }
    if (lane == 31) wsum[w] = p;
    __syncthreads();
    int wb = 0;
    for (int i = 0; i < w; i++) wb += wsum[i];
    int e0 = wb + p - tot;
    if (base + 0 < n) excl[base + 0] = e0;
    if (base + 1 < n) excl[base + 1] = e0 + v0;
    if (base + 2 < n) excl[base + 2] = e0 + v0 + v1;
    if (base + 3 < n) excl[base + 3] = e0 + v0 + v1 + v2;
    if (t == 255) bs[blockIdx.x] = wb + p;
}
__global__ void k_scan2f() {
    int y = blockIdx.x;
    int nb = (y == 2) ? (HEN + 1023) / 1024 : (NN + 1023) / 1024;
    int* b = g_bsum + y * 128;
    int t = threadIdx.x;       // 1024
    int v = (t < nb) ? b[t] : 0;
    int lane = t & 31, w = t >> 5;
    int p = v;
    for (int d = 1; d < 32; d <<= 1) { int u = __shfl_up_sync(~0u, p, d); if (lane >= d) p += u; }
    __shared__ int ws[32];
    if (lane == 31) ws[w] = p;
    __syncthreads();
    if (t < 32) {
        int q = ws[t], pp = q;
        for (int d = 1; d < 32; d <<= 1) { int u = __shfl_up_sync(~0u, pp, d); if (t >= d) pp += u; }
        ws[t] = pp - q;
    }
    __syncthreads();
    if (t < nb) b[t] = ws[w] + p - v;
}
__global__ void k_scan3f() {  // offsets += block base; init cursors; fold norms in y==0
    int i = blockIdx.x * blockDim.x + threadIdx.x;
    int y = blockIdx.y;
    if (y == 0) {
        if (i < NN) {
            int v = g_offE[i] + g_bsum[i >> 10];
            g_offE[i] = v; g_curE[i] = v;
            g_dis[i] = rsqrtf((float)g_cntE[i] + 1.0f);
            int dn = g_cntN[i];
            g_Dninv[i] = dn > 0 ? 1.0f / (float)dn : 0.0f;
        }
        if (i < HEN) {
            int bh = g_cntH[i];
            g_Binv[i] = bh > 0 ? 1.0f / (float)bh : 0.0f;
        }
        if (i == 0) g_offE[NN] = EE;
    } else if (y == 1) {
        if (i < NN) {
            int v = g_offN[i] + g_bsum[128 + (i >> 10)];
            g_offN[i] = v; g_curN[i] = v;
        }
        if (i == 0) g_offN[NN] = PP;
    } else {
        if (i < HEN) {
            int v = g_offH[i] + g_bsum[256 + (i >> 10)];
            g_offH[i] = v; g_curH[i] = v;
        }
        if (i == 0) g_offH[HEN] = PP;
    }
}

// ---------------- fused CSR fill (+ re-zero counts for the next replay) ----------------
__global__ void k_fill(const void* eidx, const void* hidx) {
    int me = sniff64(eidx), mh = sniff64(hidx);
    int i = blockIdx.x * blockDim.x + threadIdx.x;
    if (i < EE) {
        int src = (int)ldidx(eidx, i, me);
        int dst = (int)ldidx(eidx, (long long)EE + i, me);
        int pos = atomicAdd(&g_curE[dst], 1);
        g_csrE[pos] = src;
    }
    if (i < PP) {
        int node = (int)ldidx(hidx, i, mh);
        int he   = (int)ldidx(hidx, (long long)PP + i, mh);
        int p1 = atomicAdd(&g_curH[he], 1);   g_csrHn[p1] = node;
        int p2 = atomicAdd(&g_curN[node], 1); g_csrNh[p2] = he;
    }
    // counts are consumed (scan1/scan3 ran before this kernel); zero them so the
    // next kernel_launch invocation / graph replay starts from the same state
    if (i < NN) { g_cntE[i] = 0; g_cntN[i] = 0; }
    if (i < HEN) g_cntH[i] = 0;
}

// ---------------- register-tiled GEMM: out = rowscale * ([A1|A2] @ W) + bias ----------------
template<int K1, int K2, int C>
__global__ void k_gemm(const float* __restrict__ A1, const float* __restrict__ A2,
                       const float* __restrict__ W, float* __restrict__ out,
                       const float* __restrict__ rowscale, const float* __restrict__ bias) {
    constexpr int KT = K1 + K2;
    constexpr int CG = C / 4;
    __shared__ float Ws[KT * C];
    int tid = threadIdx.x;                     // CG*16 threads
    for (int i = tid; i < KT * C; i += CG * 16) Ws[i] = W[i];
    __syncthreads();
    int cg = tid % CG, rg = tid / CG;
    int row0 = blockIdx.x * 64 + rg * 4;
    int r[4];
    #pragma unroll
    for (int j = 0; j < 4; j++) { int rr = row0 + j; r[j] = rr < NN ? rr : NN - 1; }

    float acc[4][4] = {};
    #pragma unroll 2
    for (int k = 0; k < K1; k += 4) {
        float a[4][4];
        #pragma unroll
        for (int j = 0; j < 4; j++)
            *(float4*)a[j] = *(const float4*)(A1 + (size_t)r[j] * K1 + k);
        #pragma unroll
        for (int kk = 0; kk < 4; kk++) {
            float w[4];
            *(float4*)w = *(const float4*)&Ws[(k + kk) * C + cg * 4];
            #pragma unroll
            for (int j = 0; j < 4; j++)
                #pragma unroll
                for (int c = 0; c < 4; c++)
                    acc[j][c] = fmaf(a[j][kk], w[c], acc[j][c]);
        }
    }
    if (K2 > 0) {
        #pragma unroll 2
        for (int k = 0; k < K2; k += 4) {
            float a[4][4];
            #pragma unroll
            for (int j = 0; j < 4; j++)
                *(float4*)a[j] = *(const float4*)(A2 + (size_t)r[j] * K2 + k);
            #pragma unroll
            for (int kk = 0; kk < 4; kk++) {
                float w[4];
                *(float4*)w = *(const float4*)&Ws[(K1 + k + kk) * C + cg * 4];
                #pragma unroll
                for (int j = 0; j < 4; j++)
                    #pragma unroll
                    for (int c = 0; c < 4; c++)
                        acc[j][c] = fmaf(a[j][kk], w[c], acc[j][c]);
            }
        }
    }
    #pragma unroll
    for (int j = 0; j < 4; j++) {
        int rr = row0 + j;
        if (rr >= NN) break;
        float s = rowscale ? rowscale[rr] : 1.0f;
        float4 o;
        o.x = acc[j][0] * s; o.y = acc[j][1] * s; o.z = acc[j][2] * s; o.w = acc[j][3] * s;
        if (bias) {
            const float4 bb = *(const float4*)(bias + cg * 4);
            o.x += bb.x; o.y += bb.y; o.z += bb.z; o.w += bb.w;
        }
        *(float4*)(out + (size_t)rr * C + cg * 4) = o;
    }
}

// ---------------- gathers (CSR, register accumulate, fused epilogues) ----------------
#define ACC4(acc, v) { acc.x += v.x; acc.y += v.y; acc.z += v.z; acc.w += v.w; }

__global__ void k_gath_he(const float* __restrict__ xw) {
    int t = blockIdx.x * blockDim.x + threadIdx.x;
    int he = t >> 4, l = t & 15;
    if (he >= HEN) return;
    int s = g_offH[he], e = g_offH[he + 1];
    float4 acc = make_float4(0.f, 0.f, 0.f, 0.f);
    int i = s;
    for (; i + 3 < e; i += 4) {
        int n0 = g_csrHn[i], n1 = g_csrHn[i + 1], n2 = g_csrHn[i + 2], n3 = g_csrHn[i + 3];
        float4 v0 = *(const float4*)(xw + (size_t)n0 * D + l * 4);
        float4 v1 = *(const float4*)(xw + (size_t)n1 * D + l * 4);
        float4 v2 = *(const float4*)(xw + (size_t)n2 * D + l * 4);
        float4 v3 = *(const float4*)(xw + (size_t)n3 * D + l * 4);
        ACC4(acc, v0); ACC4(acc, v1); ACC4(acc, v2); ACC4(acc, v3);
    }
    for (; i < e; i++) {
        int n0 = g_csrHn[i];
        float4 v0 = *(const float4*)(xw + (size_t)n0 * D + l * 4);
        ACC4(acc, v0);
    }
    float b = g_Binv[he];
    acc.x *= b; acc.y *= b; acc.z *= b; acc.w *= b;
    *(float4*)(g_ef + (size_t)he * D + l * 4) = acc;
}

__global__ void k_gath_e2n(const float* __restrict__ bias, float* __restrict__ out, int relu) {
    int t = blockIdx.x * blockDim.x + threadIdx.x;
    int node = t >> 4, l = t & 15;
    if (node >= NN) return;
    int s = g_offN[node], e = g_offN[node + 1];
    float4 acc = make_float4(0.f, 0.f, 0.f, 0.f);
    int i = s;
    for (; i + 3 < e; i += 4) {
        int h0 = g_csrNh[i], h1 = g_csrNh[i + 1], h2 = g_csrNh[i + 2], h3 = g_csrNh[i + 3];
        float4 v0 = *(const float4*)(g_ef + (size_t)h0 * D + l * 4);
        float4 v1 = *(const float4*)(g_ef + (size_t)h1 * D + l * 4);
        float4 v2 = *(const float4*)(g_ef + (size_t)h2 * D + l * 4);
        float4 v3 = *(const float4*)(g_ef + (size_t)h3 * D + l * 4);
        ACC4(acc, v0); ACC4(acc, v1); ACC4(acc, v2); ACC4(acc, v3);
    }
    for (; i < e; i++) {
        int h0 = g_csrNh[i];
        float4 v0 = *(const float4*)(g_ef + (size_t)h0 * D + l * 4);
        ACC4(acc, v0);
    }
    float dv = g_Dninv[node];
    float4 bb = *(const float4*)(bias + l * 4);
    float4 o;
    o.x = dv * acc.x + bb.x; o.y = dv * acc.y + bb.y;
    o.z = dv * acc.z + bb.z; o.w = dv * acc.w + bb.w;
    if (relu) {
        o.x = fmaxf(o.x, 0.f); o.y = fmaxf(o.y, 0.f);
        o.z = fmaxf(o.z, 0.f); o.w = fmaxf(o.w, 0.f);
    }
    *(float4*)(out + (size_t)node * D + l * 4) = o;
}

__global__ void k_gcn64(const float* __restrict__ xwd, const float* __restrict__ bias,
                        float* __restrict__ out) {
    int t = blockIdx.x * blockDim.x + threadIdx.x;
    int node = t >> 4, l = t & 15;
    if (node >= NN) return;
    int s = g_offE[node], e = g_offE[node + 1];
    float4 acc = make_float4(0.f, 0.f, 0.f, 0.f);
    int i = s;
    for (; i + 3 < e; i += 4) {
        int s0 = g_csrE[i], s1 = g_csrE[i + 1], s2 = g_csrE[i + 2], s3 = g_csrE[i + 3];
        float4 v0 = *(const float4*)(xwd + (size_t)s0 * D + l * 4);
        float4 v1 = *(const float4*)(xwd + (size_t)s1 * D + l * 4);
        float4 v2 = *(const float4*)(xwd + (size_t)s2 * D + l * 4);
        float4 v3 = *(const float4*)(xwd + (size_t)s3 * D + l * 4);
        ACC4(acc, v0); ACC4(acc, v1); ACC4(acc, v2); ACC4(acc, v3);
    }
    for (; i < e; i++) {
        int s0 = g_csrE[i];
        float4 v0 = *(const float4*)(xwd + (size_t)s0 * D + l * 4);
        ACC4(acc, v0);
    }
    float4 self = *(const float4*)(xwd + (size_t)node * D + l * 4);
    float ds = g_dis[node];
    float4 bb = *(const float4*)(bias + l * 4);
    float4 o;
    o.x = fmaxf(ds * (acc.x + self.x) + bb.x, 0.f);
    o.y = fmaxf(ds * (acc.y + self.y) + bb.y, 0.f);
    o.z = fmaxf(ds * (acc.z + self.z) + bb.z, 0.f);
    o.w = fmaxf(ds * (acc.w + self.w) + bb.w, 0.f);
    *(float4*)(out + (size_t)node * D + l * 4) = o;
}

__global__ void k_gcn40(const float* __restrict__ bias, float* __restrict__ out) {
    int t = blockIdx.x * blockDim.x + threadIdx.x;   // 10 lanes per node
    int node = t / 10, l = t % 10;
    if (node >= NN) return;
    int s = g_offE[node], e = g_offE[node + 1];
    float4 acc = make_float4(0.f, 0.f, 0.f, 0.f);
    int i = s;
    for (; i + 3 < e; i += 4) {
        int s0 = g_csrE[i], s1 = g_csrE[i + 1], s2 = g_csrE[i + 2], s3 = g_csrE[i + 3];
        float4 v0 = *(const float4*)(g_t40 + (size_t)s0 * NC + l * 4);
        float4 v1 = *(const float4*)(g_t40 + (size_t)s1 * NC + l * 4);
        float4 v2 = *(const float4*)(g_t40 + (size_t)s2 * NC + l * 4);
        float4 v3 = *(const float4*)(g_t40 + (size_t)s3 * NC + l * 4);
        ACC4(acc, v0); ACC4(acc, v1); ACC4(acc, v2); ACC4(acc, v3);
    }
    for (; i < e; i++) {
        int s0 = g_csrE[i];
        float4 v0 = *(const float4*)(g_t40 + (size_t)s0 * NC + l * 4);
        ACC4(acc, v0);
    }
    float4 self = *(const float4*)(g_t40 + (size_t)node * NC + l * 4);
    float ds = g_dis[node];
    float4 bb = *(const float4*)(bias + l * 4);
    float4 o;
    o.x = ds * (acc.x + self.x) + bb.x;
    o.y = ds * (acc.y + self.y) + bb.y;
    o.z = ds * (acc.z + self.z) + bb.z;
    o.w = ds * (acc.w + self.w) + bb.w;
    *(float4*)(out + (size_t)node * NC + l * 4) = o;
}

// ---------------- launch (single stream; no stream/event creation) ----------------
extern "C" void kernel_launch(void* const* d_in, const int* in_sizes, int n_in,
                              void* d_out, int out_size) {
    const float* x    = (const float*)d_in[0];
    const void*  eidx = d_in[1];
    const void*  hidx = d_in[2];
    const float* W_h1 = (const float*)d_in[3];
    const float* b_h1 = (const float*)d_in[4];
    const float* W_h2 = (const float*)d_in[5];
    const float* b_h2 = (const float*)d_in[6];
    const float* W_c1 = (const float*)d_in[7];
    const float* b_c1 = (const float*)d_in[8];
    const float* W_c2 = (const float*)d_in[9];
    const float* b_c2 = (const float*)d_in[10];
    const float* W_lp = (const float*)d_in[11];
    const float* b_lp = (const float*)d_in[12];
    float* out = (float*)d_out;

    float *p_xw, *p_h1, *p_h2, *p_xg, *p_t40, *p_dis;
    cudaGetSymbolAddress((void**)&p_xw,  g_xw);
    cudaGetSymbolAddress((void**)&p_h1,  g_h1);
    cudaGetSymbolAddress((void**)&p_h2,  g_h2);
    cudaGetSymbolAddress((void**)&p_xg,  g_xg);
    cudaGetSymbolAddress((void**)&p_t40, g_t40);
    cudaGetSymbolAddress((void**)&p_dis, g_dis);

    const int B = 256;
    const int GR = (NN + 63) / 64;

    // ---- CSR build ----
    k_cnt<<<(EE + B - 1) / B, B>>>(eidx, hidx);
    k_scan1f<<<dim3((NN + 1023) / 1024, 3), 256>>>();
    k_scan2f<<<3, 1024>>>();
    k_scan3f<<<dim3((NN + B - 1) / B, 3), B>>>();
    k_fill<<<(EE + B - 1) / B, B>>>(eidx, hidx);

    // ---- hyperconv 1 ----
    k_gemm<FIN, 0, D><<<GR, 256>>>(x, nullptr, W_h1, p_xw, nullptr, nullptr);
    k_gath_he<<<(HEN * 16 + B - 1) / B, B>>>(p_xw);
    k_gath_e2n<<<(NN * 16 + B - 1) / B, B>>>(b_h1, p_h1, 1);

    // ---- hyperconv 2 ----
    k_gemm<D, 0, D><<<GR, 256>>>(p_h1, nullptr, W_h2, p_xw, nullptr, nullptr);
    k_gath_he<<<(HEN * 16 + B - 1) / B, B>>>(p_xw);
    k_gath_e2n<<<(NN * 16 + B - 1) / B, B>>>(b_h2, p_h2, 0);

    // ---- gcn 1 (concat input, dis-prescaled) ----
    k_gemm<FIN, D, D><<<GR, 256>>>(x, p_h2, W_c1, p_xw, p_dis, nullptr);
    k_gcn64<<<(NN * 16 + B - 1) / B, B>>>(p_xw, b_c1, p_xg);

    // ---- gcn 2 + linear head ----
    k_gemm<D, 0, NC><<<GR, 160>>>(p_xg, nullptr, W_c2, p_t40, p_dis, nullptr);
    k_gcn40<<<(NN * 10 + 319) / 320, 320>>>(b_c2, p_xw);
    k_gemm<NC, 0, NC><<<GR, 160>>>(p_xw, nullptr, W_lp, out, nullptr, b_lp);
}

// round 11
// speedup vs baseline: 1.3826x; 1.1851x over previous
#include <cuda_runtime.h>
#include <cuda_bf16.h>
#include <cstdint>

#define NN  100000
#define EE  1600000
#define PP  800000
#define HEN 20000
#define FIN 128
#define D   64
#define NC  40

// ---------------- scratch (device globals; no allocation allowed) ----------------
__device__ float g_xw [NN * D];
__device__ float g_h1 [NN * D];
__device__ float g_h2 [NN * D];
__device__ float g_xg [NN * D];
__device__ float g_t40[NN * NC];
__device__ float g_ef [HEN * D];
__device__ float g_dis  [NN];
__device__ float g_Dninv[NN];
__device__ float g_Binv [HEN];
__device__ int g_cntE[NN], g_cntH[HEN], g_cntN[NN];   // static zero-init; re-zeroed in k_fill
__device__ int g_offE[NN + 1], g_offH[HEN + 1], g_offN[NN + 1];
__device__ int g_curE[NN], g_curH[HEN], g_curN[NN];
__device__ int g_csrE[EE];
__device__ int g_csrHn[PP];
__device__ int g_csrNh[PP];
__device__ int g_bsum[512];

// ---------------- helpers ----------------
__device__ __forceinline__ int sniff64(const void* b) {
    int acc = 0;
    #pragma unroll
    for (int i = 0; i < 8; i++) acc |= ((const int*)b)[2 * i + 1];
    return acc == 0;
}
__device__ __forceinline__ long long ldidx(const void* b, long long i, int m64) {
    return m64 ? ((const long long*)b)[i] : (long long)((const int*)b)[i];
}

// ---------------- fused counting ----------------
__global__ void k_cnt(const void* eidx, const void* hidx) {
    int me = sniff64(eidx), mh = sniff64(hidx);
    int i = blockIdx.x * blockDim.x + threadIdx.x;
    if (i < EE) {
        int dst = (int)ldidx(eidx, (long long)EE + i, me);
        atomicAdd(&g_cntE[dst], 1);
    }
    if (i < PP) {
        int node = (int)ldidx(hidx, i, mh);
        int he   = (int)ldidx(hidx, (long long)PP + i, mh);
        atomicAdd(&g_cntN[node], 1);
        atomicAdd(&g_cntH[he], 1);
    }
}

// ---------------- fused exclusive scans ----------------
__global__ void k_scan1f() {
    const int* cnt; int n; int* excl; int* bs;
    if (blockIdx.y == 0)      { cnt = g_cntE; n = NN;  excl = g_offE; bs = g_bsum;       }
    else if (blockIdx.y == 1) { cnt = g_cntN; n = NN;  excl = g_offN; bs = g_bsum + 128; }
    else                      { cnt = g_cntH; n = HEN; excl = g_offH; bs = g_bsum + 256; }
    __shared__ int wsum[8];
    int t = threadIdx.x;
    int base = blockIdx.x * 1024 + t * 4;
    int v0 = 0, v1 = 0, v2 = 0, v3 = 0;
    if (base + 0 < n) v0 = cnt[base + 0];
    if (base + 1 < n) v1 = cnt[base + 1];
    if (base + 2 < n) v2 = cnt[base + 2];
    if (base + 3 < n) v3 = cnt[base + 3];
    int tot = v0 + v1 + v2 + v3;
    int lane = t & 31, w = t >> 5;
    int p = tot;
    for (int d = 1; d < 32; d <<= 1) { int u = __shfl_up_sync(~0u, p, d); if (lane >= d) p += u; }
    if (lane == 31) wsum[w] = p;
    __syncthreads();
    int wb = 0;
    for (int i = 0; i < w; i++) wb += wsum[i];
    int e0 = wb + p - tot;
    if (base + 0 < n) excl[base + 0] = e0;
    if (base + 1 < n) excl[base + 1] = e0 + v0;
    if (base + 2 < n) excl[base + 2] = e0 + v0 + v1;
    if (base + 3 < n) excl[base + 3] = e0 + v0 + v1 + v2;
    if (t == 255) bs[blockIdx.x] = wb + p;
}
__global__ void k_scan2f() {
    int y = blockIdx.x;
    int nb = (y == 2) ? (HEN + 1023) / 1024 : (NN + 1023) / 1024;
    int* b = g_bsum + y * 128;
    int t = threadIdx.x;
    int v = (t < nb) ? b[t] : 0;
    int lane = t & 31, w = t >> 5;
    int p = v;
    for (int d = 1; d < 32; d <<= 1) { int u = __shfl_up_sync(~0u, p, d); if (lane >= d) p += u; }
    __shared__ int ws[32];
    if (lane == 31) ws[w] = p;
    __syncthreads();
    if (t < 32) {
        int q = ws[t], pp = q;
        for (int d = 1; d < 32; d <<= 1) { int u = __shfl_up_sync(~0u, pp, d); if (t >= d) pp += u; }
        ws[t] = pp - q;
    }
    __syncthreads();
    if (t < nb) b[t] = ws[w] + p - v;
}
__global__ void k_scan3f() {
    int i = blockIdx.x * blockDim.x + threadIdx.x;
    int y = blockIdx.y;
    if (y == 0) {
        if (i < NN) {
            int v = g_offE[i] + g_bsum[i >> 10];
            g_offE[i] = v; g_curE[i] = v;
            g_dis[i] = rsqrtf((float)g_cntE[i] + 1.0f);
            int dn = g_cntN[i];
            g_Dninv[i] = dn > 0 ? 1.0f / (float)dn : 0.0f;
        }
        if (i < HEN) {
            int bh = g_cntH[i];
            g_Binv[i] = bh > 0 ? 1.0f / (float)bh : 0.0f;
        }
        if (i == 0) g_offE[NN] = EE;
    } else if (y == 1) {
        if (i < NN) {
            int v = g_offN[i] + g_bsum[128 + (i >> 10)];
            g_offN[i] = v; g_curN[i] = v;
        }
        if (i == 0) g_offN[NN] = PP;
    } else {
        if (i < HEN) {
            int v = g_offH[i] + g_bsum[256 + (i >> 10)];
            g_offH[i] = v; g_curH[i] = v;
        }
        if (i == 0) g_offH[HEN] = PP;
    }
}

// ---------------- fused CSR fill (+ re-zero counts for next replay) ----------------
__global__ void k_fill(const void* eidx, const void* hidx) {
    int me = sniff64(eidx), mh = sniff64(hidx);
    int i = blockIdx.x * blockDim.x + threadIdx.x;
    if (i < EE) {
        int src = (int)ldidx(eidx, i, me);
        int dst = (int)ldidx(eidx, (long long)EE + i, me);
        int pos = atomicAdd(&g_curE[dst], 1);
        g_csrE[pos] = src;
    }
    if (i < PP) {
        int node = (int)ldidx(hidx, i, mh);
        int he   = (int)ldidx(hidx, (long long)PP + i, mh);
        int p1 = atomicAdd(&g_curH[he], 1);   g_csrHn[p1] = node;
        int p2 = atomicAdd(&g_curN[node], 1); g_csrNh[p2] = he;
    }
    if (i < NN) { g_cntE[i] = 0; g_cntN[i] = 0; }
    if (i < HEN) g_cntH[i] = 0;
}

// ---------------- bf16 split tensor-core GEMM (C=64): out = rowscale * ([A1|A2] @ W) ----
// 2-term split: a = hi + lo (bf16 each); a*w ~= ah*wh + al*wh + ah*wl  (~2^-16 rel err)
// mma.sync m16n8k16 row.col: A quadrants a0..a3, B k-halves b0/b1, C rows g/g+8.
__host__ __device__ constexpr int padw(int v) { int r = v % 32; return v + ((r <= 4) ? (4 - r) : (36 - r)); }

__device__ __forceinline__ void bsplit(float2 q, uint32_t& hi, uint32_t& lo) {
    uint32_t h;
    asm("cvt.rn.bf16x2.f32 %0, %1, %2;" : "=r"(h) : "f"(q.y), "f"(q.x));  // {lo=q.x, hi=q.y}
    float hx = __uint_as_float(h << 16);
    float hy = __uint_as_float(h & 0xffff0000u);
    float rx = q.x - hx, ry = q.y - hy;
    uint32_t l;
    asm("cvt.rn.bf16x2.f32 %0, %1, %2;" : "=r"(l) : "f"(ry), "f"(rx));
    hi = h; lo = l;
}
#define MMA16816(c, a, b0, b1)                                                     \
    asm volatile("mma.sync.aligned.m16n8k16.row.col.f32.bf16.bf16.f32 "            \
                 "{%0,%1,%2,%3}, {%4,%5,%6,%7}, {%8,%9}, {%0,%1,%2,%3};"           \
                 : "+f"(c[0]), "+f"(c[1]), "+f"(c[2]), "+f"(c[3])                  \
                 : "r"(a[0]), "r"(a[1]), "r"(a[2]), "r"(a[3]), "r"(b0), "r"(b1))

template<int K1, int K2>
__global__ void k_mma(const float* __restrict__ A1, const float* __restrict__ A2,
                      const float* __restrict__ W, float* __restrict__ out,
                      const float* __restrict__ rowscale) {
    constexpr int KT = K1 + K2;
    constexpr int C = 64;
    constexpr int KPW = padw(KT / 2);   // u32 words per Wt row (bank-staggered)
    constexpr int KPE = KPW * 2;        // bf16 elems per Wt row
    extern __shared__ unsigned char smraw[];
    __nv_bfloat16* WtHi = (__nv_bfloat16*)smraw;               // [C][KPE] transposed
    __nv_bfloat16* WtLo = WtHi + C * KPE;

    int tid = threadIdx.x;
    // stage W transposed, split hi/lo (coalesced global read)
    for (int idx = tid; idx < KT * C; idx += 128) {
        int k = idx >> 6, n = idx & 63;             // C == 64
        float w = W[idx];
        __nv_bfloat16 h = __float2bfloat16(w);
        float lo = w - __bfloat162float(h);
        WtHi[n * KPE + k] = h;
        WtLo[n * KPE + k] = __float2bfloat16(lo);
    }
    __syncthreads();

    const uint32_t* WH = (const uint32_t*)WtHi;
    const uint32_t* WL = (const uint32_t*)WtLo;

    int w = tid >> 5, lane = tid & 31;
    int g = lane >> 2, t = lane & 3;
    int m0 = blockIdx.x * 128 + w * 32;
    int rows[4] = { m0 + g, m0 + g + 8, m0 + 16 + g, m0 + 24 + g };
    int rc[4];
    #pragma unroll
    for (int i = 0; i < 4; i++) rc[i] = rows[i] < NN ? rows[i] : NN - 1;

    float acc[2][8][4] = {};

    for (int kc = 0; kc < KT / 16; kc++) {
        int kk = kc * 16;
        uint32_t ah[2][4], al[2][4];
        #pragma unroll
        for (int f = 0; f < 2; f++) {
            const float *p0, *p1;
            if (K2 == 0 || kk < K1) {
                p0 = A1 + (size_t)rc[2 * f] * K1 + kk;
                p1 = A1 + (size_t)rc[2 * f + 1] * K1 + kk;
            } else {
                p0 = A2 + (size_t)rc[2 * f] * K2 + (kk - K1);
                p1 = A2 + (size_t)rc[2 * f + 1] * K2 + (kk - K1);
            }
            float2 q0 = *(const float2*)(p0 + 2 * t);       // a0: row g,   k 2t
            float2 q1 = *(const float2*)(p1 + 2 * t);       // a1: row g+8, k 2t
            float2 q2 = *(const float2*)(p0 + 2 * t + 8);   // a2: row g,   k 2t+8
            float2 q3 = *(const float2*)(p1 + 2 * t + 8);   // a3: row g+8, k 2t+8
            bsplit(q0, ah[f][0], al[f][0]);
            bsplit(q1, ah[f][1], al[f][1]);
            bsplit(q2, ah[f][2], al[f][2]);
            bsplit(q3, ah[f][3], al[f][3]);
        }
        #pragma unroll
        for (int s = 0; s < 8; s++) {
            int wi = (s * 8 + g) * KPW + kc * 8 + t;
            uint32_t bh0 = WH[wi], bh1 = WH[wi + 4];
            uint32_t bl0 = WL[wi], bl1 = WL[wi + 4];
            #pragma unroll
            for (int f = 0; f < 2; f++) {
                MMA16816(acc[f][s], ah[f], bh0, bh1);
                MMA16816(acc[f][s], al[f], bh0, bh1);
                MMA16816(acc[f][s], ah[f], bl0, bl1);
            }
        }
    }

    float rs[4] = {1.f, 1.f, 1.f, 1.f};
    if (rowscale) {
        #pragma unroll
        for (int i = 0; i < 4; i++) rs[i] = rowscale[rc[i]];
    }
    #pragma unroll
    for (int f = 0; f < 2; f++) {
        #pragma unroll
        for (int s = 0; s < 8; s++) {
            int col = s * 8 + 2 * t;
            int ra = rows[2 * f], rb = rows[2 * f + 1];
            if (ra < NN) {
                float2 v = { acc[f][s][0] * rs[2 * f], acc[f][s][1] * rs[2 * f] };
                *(float2*)(out + (size_t)ra * C + col) = v;
            }
            if (rb < NN) {
                float2 v = { acc[f][s][2] * rs[2 * f + 1], acc[f][s][3] * rs[2 * f + 1] };
                *(float2*)(out + (size_t)rb * C + col) = v;
            }
        }
    }
}

// ---------------- FFMA GEMM (kept for C=40): out = rowscale*(A@W) + bias ----------------
template<int K1, int K2, int C>
__global__ void k_gemm(const float* __restrict__ A1, const float* __restrict__ A2,
                       const float* __restrict__ W, float* __restrict__ out,
                       const float* __restrict__ rowscale, const float* __restrict__ bias) {
    constexpr int KT = K1 + K2;
    constexpr int CG = C / 4;
    __shared__ float Ws[KT * C];
    int tid = threadIdx.x;
    for (int i = tid; i < KT * C; i += CG * 16) Ws[i] = W[i];
    __syncthreads();
    int cg = tid % CG, rg = tid / CG;
    int row0 = blockIdx.x * 64 + rg * 4;
    int r[4];
    #pragma unroll
    for (int j = 0; j < 4; j++) { int rr = row0 + j; r[j] = rr < NN ? rr : NN - 1; }

    float acc[4][4] = {};
    #pragma unroll 2
    for (int k = 0; k < K1; k += 4) {
        float a[4][4];
        #pragma unroll
        for (int j = 0; j < 4; j++)
            *(float4*)a[j] = *(const float4*)(A1 + (size_t)r[j] * K1 + k);
        #pragma unroll
        for (int kk = 0; kk < 4; kk++) {
            float w[4];
            *(float4*)w = *(const float4*)&Ws[(k + kk) * C + cg * 4];
            #pragma unroll
            for (int j = 0; j < 4; j++)
                #pragma unroll
                for (int c = 0; c < 4; c++)
                    acc[j][c] = fmaf(a[j][kk], w[c], acc[j][c]);
        }
    }
    #pragma unroll
    for (int j = 0; j < 4; j++) {
        int rr = row0 + j;
        if (rr >= NN) break;
        float s = rowscale ? rowscale[rr] : 1.0f;
        float4 o;
        o.x = acc[j][0] * s; o.y = acc[j][1] * s; o.z = acc[j][2] * s; o.w = acc[j][3] * s;
        if (bias) {
            const float4 bb = *(const float4*)(bias + cg * 4);
            o.x += bb.x; o.y += bb.y; o.z += bb.z; o.w += bb.w;
        }
        *(float4*)(out + (size_t)rr * C + cg * 4) = o;
    }
}

// ---------------- gathers (CSR, register accumulate, fused epilogues) ----------------
#define ACC4(acc, v) { acc.x += v.x; acc.y += v.y; acc.z += v.z; acc.w += v.w; }

__global__ void k_gath_he(const float* __restrict__ xw) {
    int t = blockIdx.x * blockDim.x + threadIdx.x;
    int he = t >> 4, l = t & 15;
    if (he >= HEN) return;
    int s = g_offH[he], e = g_offH[he + 1];
    float4 acc = make_float4(0.f, 0.f, 0.f, 0.f);
    int i = s;
    for (; i + 3 < e; i += 4) {
        int n0 = g_csrHn[i], n1 = g_csrHn[i + 1], n2 = g_csrHn[i + 2], n3 = g_csrHn[i + 3];
        float4 v0 = *(const float4*)(xw + (size_t)n0 * D + l * 4);
        float4 v1 = *(const float4*)(xw + (size_t)n1 * D + l * 4);
        float4 v2 = *(const float4*)(xw + (size_t)n2 * D + l * 4);
        float4 v3 = *(const float4*)(xw + (size_t)n3 * D + l * 4);
        ACC4(acc, v0); ACC4(acc, v1); ACC4(acc, v2); ACC4(acc, v3);
    }
    for (; i < e; i++) {
        int n0 = g_csrHn[i];
        float4 v0 = *(const float4*)(xw + (size_t)n0 * D + l * 4);
        ACC4(acc, v0);
    }
    float b = g_Binv[he];
    acc.x *= b; acc.y *= b; acc.z *= b; acc.w *= b;
    *(float4*)(g_ef + (size_t)he * D + l * 4) = acc;
}

__global__ void k_gath_e2n(const float* __restrict__ bias, float* __restrict__ out, int relu) {
    int t = blockIdx.x * blockDim.x + threadIdx.x;
    int node = t >> 4, l = t & 15;
    if (node >= NN) return;
    int s = g_offN[node], e = g_offN[node + 1];
    float4 acc = make_float4(0.f, 0.f, 0.f, 0.f);
    int i = s;
    for (; i + 3 < e; i += 4) {
        int h0 = g_csrNh[i], h1 = g_csrNh[i + 1], h2 = g_csrNh[i + 2], h3 = g_csrNh[i + 3];
        float4 v0 = *(const float4*)(g_ef + (size_t)h0 * D + l * 4);
        float4 v1 = *(const float4*)(g_ef + (size_t)h1 * D + l * 4);
        float4 v2 = *(const float4*)(g_ef + (size_t)h2 * D + l * 4);
        float4 v3 = *(const float4*)(g_ef + (size_t)h3 * D + l * 4);
        ACC4(acc, v0); ACC4(acc, v1); ACC4(acc, v2); ACC4(acc, v3);
    }
    for (; i < e; i++) {
        int h0 = g_csrNh[i];
        float4 v0 = *(const float4*)(g_ef + (size_t)h0 * D + l * 4);
        ACC4(acc, v0);
    }
    float dv = g_Dninv[node];
    float4 bb = *(const float4*)(bias + l * 4);
    float4 o;
    o.x = dv * acc.x + bb.x; o.y = dv * acc.y + bb.y;
    o.z = dv * acc.z + bb.z; o.w = dv * acc.w + bb.w;
    if (relu) {
        o.x = fmaxf(o.x, 0.f); o.y = fmaxf(o.y, 0.f);
        o.z = fmaxf(o.z, 0.f); o.w = fmaxf(o.w, 0.f);
    }
    *(float4*)(out + (size_t)node * D + l * 4) = o;
}

__global__ void k_gcn64(const float* __restrict__ xwd, const float* __restrict__ bias,
                        float* __restrict__ out) {
    int t = blockIdx.x * blockDim.x + threadIdx.x;
    int node = t >> 4, l = t & 15;
    if (node >= NN) return;
    int s = g_offE[node], e = g_offE[node + 1];
    float4 acc = make_float4(0.f, 0.f, 0.f, 0.f);
    int i = s;
    for (; i + 3 < e; i += 4) {
        int s0 = g_csrE[i], s1 = g_csrE[i + 1], s2 = g_csrE[i + 2], s3 = g_csrE[i + 3];
        float4 v0 = *(const float4*)(xwd + (size_t)s0 * D + l * 4);
        float4 v1 = *(const float4*)(xwd + (size_t)s1 * D + l * 4);
        float4 v2 = *(const float4*)(xwd + (size_t)s2 * D + l * 4);
        float4 v3 = *(const float4*)(xwd + (size_t)s3 * D + l * 4);
        ACC4(acc, v0); ACC4(acc, v1); ACC4(acc, v2); ACC4(acc, v3);
    }
    for (; i < e; i++) {
        int s0 = g_csrE[i];
        float4 v0 = *(const float4*)(xwd + (size_t)s0 * D + l * 4);
        ACC4(acc, v0);
    }
    float4 self = *(const float4*)(xwd + (size_t)node * D + l * 4);
    float ds = g_dis[node];
    float4 bb = *(const float4*)(bias + l * 4);
    float4 o;
    o.x = fmaxf(ds * (acc.x + self.x) + bb.x, 0.f);
    o.y = fmaxf(ds * (acc.y + self.y) + bb.y, 0.f);
    o.z = fmaxf(ds * (acc.z + self.z) + bb.z, 0.f);
    o.w = fmaxf(ds * (acc.w + self.w) + bb.w, 0.f);
    *(float4*)(out + (size_t)node * D + l * 4) = o;
}

__global__ void k_gcn40(const float* __restrict__ bias, float* __restrict__ out) {
    int t = blockIdx.x * blockDim.x + threadIdx.x;
    int node = t / 10, l = t % 10;
    if (node >= NN) return;
    int s = g_offE[node], e = g_offE[node + 1];
    float4 acc = make_float4(0.f, 0.f, 0.f, 0.f);
    int i = s;
    for (; i + 3 < e; i += 4) {
        int s0 = g_csrE[i], s1 = g_csrE[i + 1], s2 = g_csrE[i + 2], s3 = g_csrE[i + 3];
        float4 v0 = *(const float4*)(g_t40 + (size_t)s0 * NC + l * 4);
        float4 v1 = *(const float4*)(g_t40 + (size_t)s1 * NC + l * 4);
        float4 v2 = *(const float4*)(g_t40 + (size_t)s2 * NC + l * 4);
        float4 v3 = *(const float4*)(g_t40 + (size_t)s3 * NC + l * 4);
        ACC4(acc, v0); ACC4(acc, v1); ACC4(acc, v2); ACC4(acc, v3);
    }
    for (; i < e; i++) {
        int s0 = g_csrE[i];
        float4 v0 = *(const float4*)(g_t40 + (size_t)s0 * NC + l * 4);
        ACC4(acc, v0);
    }
    float4 self = *(const float4*)(g_t40 + (size_t)node * NC + l * 4);
    float ds = g_dis[node];
    float4 bb = *(const float4*)(bias + l * 4);
    float4 o;
    o.x = ds * (acc.x + self.x) + bb.x;
    o.y = ds * (acc.y + self.y) + bb.y;
    o.z = ds * (acc.z + self.z) + bb.z;
    o.w = ds * (acc.w + self.w) + bb.w;
    *(float4*)(out + (size_t)node * NC + l * 4) = o;
}

// ---------------- launch (single stream) ----------------
extern "C" void kernel_launch(void* const* d_in, const int* in_sizes, int n_in,
                              void* d_out, int out_size) {
    const float* x    = (const float*)d_in[0];
    const void*  eidx = d_in[1];
    const void*  hidx = d_in[2];
    const float* W_h1 = (const float*)d_in[3];
    const float* b_h1 = (const float*)d_in[4];
    const float* W_h2 = (const float*)d_in[5];
    const float* b_h2 = (const float*)d_in[6];
    const float* W_c1 = (const float*)d_in[7];
    const float* b_c1 = (const float*)d_in[8];
    const float* W_c2 = (const float*)d_in[9];
    const float* b_c2 = (const float*)d_in[10];
    const float* W_lp = (const float*)d_in[11];
    const float* b_lp = (const float*)d_in[12];
    float* out = (float*)d_out;

    float *p_xw, *p_h1, *p_h2, *p_xg, *p_t40, *p_dis;
    cudaGetSymbolAddress((void**)&p_xw,  g_xw);
    cudaGetSymbolAddress((void**)&p_h1,  g_h1);
    cudaGetSymbolAddress((void**)&p_h2,  g_h2);
    cudaGetSymbolAddress((void**)&p_xg,  g_xg);
    cudaGetSymbolAddress((void**)&p_t40, g_t40);
    cudaGetSymbolAddress((void**)&p_dis, g_dis);

    const int B = 256;
    const int GR  = (NN + 63) / 64;     // FFMA gemm grid
    const int GRM = (NN + 127) / 128;   // mma gemm grid

    // dynamic smem sizes: 2 * C(64) * KPW * 4 bytes
    const int SH128 = 2 * 64 * padw(128 / 2) * 4;   // 34816
    const int SH64  = 2 * 64 * padw(64 / 2) * 4;    // 18432
    const int SH192 = 2 * 64 * padw(192 / 2) * 4;   // 51200 (>48KB -> needs attr)
    cudaFuncSetAttribute(k_mma<FIN, 0>, cudaFuncAttributeMaxDynamicSharedMemorySize, SH128);
    cudaFuncSetAttribute(k_mma<D, 0>,   cudaFuncAttributeMaxDynamicSharedMemorySize, SH64);
    cudaFuncSetAttribute(k_mma<FIN, D>, cudaFuncAttributeMaxDynamicSharedMemorySize, SH192);

    // ---- CSR build ----
    k_cnt<<<(EE + B - 1) / B, B>>>(eidx, hidx);
    k_scan1f<<<dim3((NN + 1023) / 1024, 3), 256>>>();
    k_scan2f<<<3, 1024>>>();
    k_scan3f<<<dim3((NN + B - 1) / B, 3), B>>>();
    k_fill<<<(EE + B - 1) / B, B>>>(eidx, hidx);

    // ---- hyperconv 1 ----
    k_mma<FIN, 0><<<GRM, 128, SH128>>>(x, nullptr, W_h1, p_xw, nullptr);
    k_gath_he<<<(HEN * 16 + B - 1) / B, B>>>(p_xw);
    k_gath_e2n<<<(NN * 16 + B - 1) / B, B>>>(b_h1, p_h1, 1);

    // ---- hyperconv 2 ----
    k_mma<D, 0><<<GRM, 128, SH64>>>(p_h1, nullptr, W_h2, p_xw, nullptr);
    k_gath_he<<<(HEN * 16 + B - 1) / B, B>>>(p_xw);
    k_gath_e2n<<<(NN * 16 + B - 1) / B, B>>>(b_h2, p_h2, 0);

    // ---- gcn 1 (concat input, dis-prescaled) ----
    k_mma<FIN, D><<<GRM, 128, SH192>>>(x, p_h2, W_c1, p_xw, p_dis);
    k_gcn64<<<(NN * 16 + B - 1) / B, B>>>(p_xw, b_c1, p_xg);

    // ---- gcn 2 + linear head ----
    k_gemm<D, 0, NC><<<GR, 160>>>(p_xg, nullptr, W_c2, p_t40, p_dis, nullptr);
    k_gcn40<<<(NN * 10 + 319) / 320, 320>>>(b_c2, p_xw);
    k_gemm<NC, 0, NC><<<GR, 160>>>(p_xw, nullptr, W_lp, out, nullptr, b_lp);
}

// round 12
// speedup vs baseline: 1.4152x; 1.0236x over previous
#include <cuda_runtime.h>
#include <cuda_bf16.h>
#include <cstdint>

#define NN  100000
#define EE  1600000
#define PP  800000
#define HEN 20000
#define FIN 128
#define D   64
#define NC  40

// ---------------- scratch (device globals; no allocation allowed) ----------------
__device__ float g_xw [NN * D];
__device__ float g_h1 [NN * D];
__device__ float g_h2 [NN * D];
__device__ float g_xg [NN * D];
__device__ float g_t40[NN * NC];
__device__ float g_ef [HEN * D];
__device__ float g_dis  [NN];
__device__ float g_Dninv[NN];
__device__ float g_Binv [HEN];
__device__ float g_Wp[D * NC];      // W_c2 @ W_lp
__device__ float g_bp[NC];          // b_c2 @ W_lp + b_lp
__device__ int g_cntE[NN], g_cntH[HEN], g_cntN[NN];   // static zero-init; re-zeroed in k_fill
__device__ int g_offE[NN + 1], g_offH[HEN + 1], g_offN[NN + 1];
__device__ int g_curE[NN], g_curH[HEN], g_curN[NN];
__device__ int g_csrE[EE];
__device__ int g_csrHn[PP];
__device__ int g_csrNh[PP];
__device__ int g_bsum[512];

// ---------------- helpers ----------------
__device__ __forceinline__ int sniff64(const void* b) {
    int acc = 0;
    #pragma unroll
    for (int i = 0; i < 8; i++) acc |= ((const int*)b)[2 * i + 1];
    return acc == 0;
}
__device__ __forceinline__ long long ldidx(const void* b, long long i, int m64) {
    return m64 ? ((const long long*)b)[i] : (long long)((const int*)b)[i];
}

// ---------------- fused counting ----------------
__global__ void k_cnt(const void* eidx, const void* hidx) {
    int me = sniff64(eidx), mh = sniff64(hidx);
    int i = blockIdx.x * blockDim.x + threadIdx.x;
    if (i < EE) {
        int dst = (int)ldidx(eidx, (long long)EE + i, me);
        atomicAdd(&g_cntE[dst], 1);
    }
    if (i < PP) {
        int node = (int)ldidx(hidx, i, mh);
        int he   = (int)ldidx(hidx, (long long)PP + i, mh);
        atomicAdd(&g_cntN[node], 1);
        atomicAdd(&g_cntH[he], 1);
    }
}

// ---------------- fused exclusive scans ----------------
__global__ void k_scan1f() {
    const int* cnt; int n; int* excl; int* bs;
    if (blockIdx.y == 0)      { cnt = g_cntE; n = NN;  excl = g_offE; bs = g_bsum;       }
    else if (blockIdx.y == 1) { cnt = g_cntN; n = NN;  excl = g_offN; bs = g_bsum + 128; }
    else                      { cnt = g_cntH; n = HEN; excl = g_offH; bs = g_bsum + 256; }
    __shared__ int wsum[8];
    int t = threadIdx.x;
    int base = blockIdx.x * 1024 + t * 4;
    int v0 = 0, v1 = 0, v2 = 0, v3 = 0;
    if (base + 0 < n) v0 = cnt[base + 0];
    if (base + 1 < n) v1 = cnt[base + 1];
    if (base + 2 < n) v2 = cnt[base + 2];
    if (base + 3 < n) v3 = cnt[base + 3];
    int tot = v0 + v1 + v2 + v3;
    int lane = t & 31, w = t >> 5;
    int p = tot;
    for (int d = 1; d < 32; d <<= 1) { int u = __shfl_up_sync(~0u, p, d); if (lane >= d) p += u; }
    if (lane == 31) wsum[w] = p;
    __syncthreads();
    int wb = 0;
    for (int i = 0; i < w; i++) wb += wsum[i];
    int e0 = wb + p - tot;
    if (base + 0 < n) excl[base + 0] = e0;
    if (base + 1 < n) excl[base + 1] = e0 + v0;
    if (base + 2 < n) excl[base + 2] = e0 + v0 + v1;
    if (base + 3 < n) excl[base + 3] = e0 + v0 + v1 + v2;
    if (t == 255) bs[blockIdx.x] = wb + p;
}
// blocks 0..2: scan block sums; block 3: fold W_lp into W_c2 (free ride, no extra launch)
__global__ void k_scan2f(const float* __restrict__ W_c2, const float* __restrict__ b_c2,
                         const float* __restrict__ W_lp, const float* __restrict__ b_lp) {
    int y = blockIdx.x;
    int t = threadIdx.x;
    if (y == 3) {
        for (int i = t; i < D * NC + NC; i += 1024) {
            if (i < D * NC) {
                int k = i / NC, c = i - k * NC;
                float s = 0.f;
                #pragma unroll
                for (int j = 0; j < NC; j++) s = fmaf(W_c2[k * NC + j], W_lp[j * NC + c], s);
                g_Wp[i] = s;
            } else {
                int c = i - D * NC;
                float s = b_lp[c];
                #pragma unroll
                for (int j = 0; j < NC; j++) s = fmaf(b_c2[j], W_lp[j * NC + c], s);
                g_bp[c] = s;
            }
        }
        return;
    }
    int nb = (y == 2) ? (HEN + 1023) / 1024 : (NN + 1023) / 1024;
    int* b = g_bsum + y * 128;
    int v = (t < nb) ? b[t] : 0;
    int lane = t & 31, w = t >> 5;
    int p = v;
    for (int d = 1; d < 32; d <<= 1) { int u = __shfl_up_sync(~0u, p, d); if (lane >= d) p += u; }
    __shared__ int ws[32];
    if (lane == 31) ws[w] = p;
    __syncthreads();
    if (t < 32) {
        int q = ws[t], pp = q;
        for (int d = 1; d < 32; d <<= 1) { int u = __shfl_up_sync(~0u, pp, d); if (t >= d) pp += u; }
        ws[t] = pp - q;
    }
    __syncthreads();
    if (t < nb) b[t] = ws[w] + p - v;
}
__global__ void k_scan3f() {
    int i = blockIdx.x * blockDim.x + threadIdx.x;
    int y = blockIdx.y;
    if (y == 0) {
        if (i < NN) {
            int v = g_offE[i] + g_bsum[i >> 10];
            g_offE[i] = v; g_curE[i] = v;
            g_dis[i] = rsqrtf((float)g_cntE[i] + 1.0f);
            int dn = g_cntN[i];
            g_Dninv[i] = dn > 0 ? 1.0f / (float)dn : 0.0f;
        }
        if (i < HEN) {
            int bh = g_cntH[i];
            g_Binv[i] = bh > 0 ? 1.0f / (float)bh : 0.0f;
        }
        if (i == 0) g_offE[NN] = EE;
    } else if (y == 1) {
        if (i < NN) {
            int v = g_offN[i] + g_bsum[128 + (i >> 10)];
            g_offN[i] = v; g_curN[i] = v;
        }
        if (i == 0) g_offN[NN] = PP;
    } else {
        if (i < HEN) {
            int v = g_offH[i] + g_bsum[256 + (i >> 10)];
            g_offH[i] = v; g_curH[i] = v;
        }
        if (i == 0) g_offH[HEN] = PP;
    }
}

// ---------------- fused CSR fill (+ re-zero counts for next replay) ----------------
__global__ void k_fill(const void* eidx, const void* hidx) {
    int me = sniff64(eidx), mh = sniff64(hidx);
    int i = blockIdx.x * blockDim.x + threadIdx.x;
    if (i < EE) {
        int src = (int)ldidx(eidx, i, me);
        int dst = (int)ldidx(eidx, (long long)EE + i, me);
        int pos = atomicAdd(&g_curE[dst], 1);
        g_csrE[pos] = src;
    }
    if (i < PP) {
        int node = (int)ldidx(hidx, i, mh);
        int he   = (int)ldidx(hidx, (long long)PP + i, mh);
        int p1 = atomicAdd(&g_curH[he], 1);   g_csrHn[p1] = node;
        int p2 = atomicAdd(&g_curN[node], 1); g_csrNh[p2] = he;
    }
    if (i < NN) { g_cntE[i] = 0; g_cntN[i] = 0; }
    if (i < HEN) g_cntH[i] = 0;
}

// ---------------- bf16 split tensor-core GEMM (C=64): out = rowscale * ([A1|A2] @ W) ----
__host__ __device__ constexpr int padw(int v) { int r = v % 32; return v + ((r <= 4) ? (4 - r) : (36 - r)); }

__device__ __forceinline__ void bsplit(float2 q, uint32_t& hi, uint32_t& lo) {
    uint32_t h;
    asm("cvt.rn.bf16x2.f32 %0, %1, %2;" : "=r"(h) : "f"(q.y), "f"(q.x));
    float hx = __uint_as_float(h << 16);
    float hy = __uint_as_float(h & 0xffff0000u);
    float rx = q.x - hx, ry = q.y - hy;
    uint32_t l;
    asm("cvt.rn.bf16x2.f32 %0, %1, %2;" : "=r"(l) : "f"(ry), "f"(rx));
    hi = h; lo = l;
}
#define MMA16816(c, a, b0, b1)                                                     \
    asm volatile("mma.sync.aligned.m16n8k16.row.col.f32.bf16.bf16.f32 "            \
                 "{%0,%1,%2,%3}, {%4,%5,%6,%7}, {%8,%9}, {%0,%1,%2,%3};"           \
                 : "+f"(c[0]), "+f"(c[1]), "+f"(c[2]), "+f"(c[3])                  \
                 : "r"(a[0]), "r"(a[1]), "r"(a[2]), "r"(a[3]), "r"(b0), "r"(b1))

template<int K1, int K2>
__global__ void k_mma(const float* __restrict__ A1, const float* __restrict__ A2,
                      const float* __restrict__ W, float* __restrict__ out,
                      const float* __restrict__ rowscale) {
    constexpr int KT = K1 + K2;
    constexpr int C = 64;
    constexpr int KPW = padw(KT / 2);
    constexpr int KPE = KPW * 2;
    extern __shared__ unsigned char smraw[];
    __nv_bfloat16* WtHi = (__nv_bfloat16*)smraw;
    __nv_bfloat16* WtLo = WtHi + C * KPE;

    int tid = threadIdx.x;
    for (int idx = tid; idx < KT * C; idx += 128) {
        int k = idx >> 6, n = idx & 63;
        float w = W[idx];
        __nv_bfloat16 h = __float2bfloat16(w);
        float lo = w - __bfloat162float(h);
        WtHi[n * KPE + k] = h;
        WtLo[n * KPE + k] = __float2bfloat16(lo);
    }
    __syncthreads();

    const uint32_t* WH = (const uint32_t*)WtHi;
    const uint32_t* WL = (const uint32_t*)WtLo;

    int w = tid >> 5, lane = tid & 31;
    int g = lane >> 2, t = lane & 3;
    int m0 = blockIdx.x * 128 + w * 32;
    int rows[4] = { m0 + g, m0 + g + 8, m0 + 16 + g, m0 + 24 + g };
    int rc[4];
    #pragma unroll
    for (int i = 0; i < 4; i++) rc[i] = rows[i] < NN ? rows[i] : NN - 1;

    float acc[2][8][4] = {};

    for (int kc = 0; kc < KT / 16; kc++) {
        int kk = kc * 16;
        uint32_t ah[2][4], al[2][4];
        #pragma unroll
        for (int f = 0; f < 2; f++) {
            const float *p0, *p1;
            if (K2 == 0 || kk < K1) {
                p0 = A1 + (size_t)rc[2 * f] * K1 + kk;
                p1 = A1 + (size_t)rc[2 * f + 1] * K1 + kk;
            } else {
                p0 = A2 + (size_t)rc[2 * f] * K2 + (kk - K1);
                p1 = A2 + (size_t)rc[2 * f + 1] * K2 + (kk - K1);
            }
            float2 q0 = *(const float2*)(p0 + 2 * t);
            float2 q1 = *(const float2*)(p1 + 2 * t);
            float2 q2 = *(const float2*)(p0 + 2 * t + 8);
            float2 q3 = *(const float2*)(p1 + 2 * t + 8);
            bsplit(q0, ah[f][0], al[f][0]);
            bsplit(q1, ah[f][1], al[f][1]);
            bsplit(q2, ah[f][2], al[f][2]);
            bsplit(q3, ah[f][3], al[f][3]);
        }
        #pragma unroll
        for (int s = 0; s < 8; s++) {
            int wi = (s * 8 + g) * KPW + kc * 8 + t;
            uint32_t bh0 = WH[wi], bh1 = WH[wi + 4];
            uint32_t bl0 = WL[wi], bl1 = WL[wi + 4];
            #pragma unroll
            for (int f = 0; f < 2; f++) {
                MMA16816(acc[f][s], ah[f], bh0, bh1);
                MMA16816(acc[f][s], al[f], bh0, bh1);
                MMA16816(acc[f][s], ah[f], bl0, bl1);
            }
        }
    }

    float rs[4] = {1.f, 1.f, 1.f, 1.f};
    if (rowscale) {
        #pragma unroll
        for (int i = 0; i < 4; i++) rs[i] = rowscale[rc[i]];
    }
    #pragma unroll
    for (int f = 0; f < 2; f++) {
        #pragma unroll
        for (int s = 0; s < 8; s++) {
            int col = s * 8 + 2 * t;
            int ra = rows[2 * f], rb = rows[2 * f + 1];
            if (ra < NN) {
                float2 v = { acc[f][s][0] * rs[2 * f], acc[f][s][1] * rs[2 * f] };
                *(float2*)(out + (size_t)ra * C + col) = v;
            }
            if (rb < NN) {
                float2 v = { acc[f][s][2] * rs[2 * f + 1], acc[f][s][3] * rs[2 * f + 1] };
                *(float2*)(out + (size_t)rb * C + col) = v;
            }
        }
    }
}

// ---------------- FFMA GEMM (C=40, W from device global): out = rowscale*(A@W) --------
template<int K1, int C>
__global__ void k_gemm(const float* __restrict__ A1, const float* __restrict__ W,
                       float* __restrict__ out, const float* __restrict__ rowscale) {
    constexpr int CG = C / 4;
    __shared__ float Ws[K1 * C];
    int tid = threadIdx.x;
    for (int i = tid; i < K1 * C; i += CG * 16) Ws[i] = W[i];
    __syncthreads();
    int cg = tid % CG, rg = tid / CG;
    int row0 = blockIdx.x * 64 + rg * 4;
    int r[4];
    #pragma unroll
    for (int j = 0; j < 4; j++) { int rr = row0 + j; r[j] = rr < NN ? rr : NN - 1; }

    float acc[4][4] = {};
    #pragma unroll 2
    for (int k = 0; k < K1; k += 4) {
        float a[4][4];
        #pragma unroll
        for (int j = 0; j < 4; j++)
            *(float4*)a[j] = *(const float4*)(A1 + (size_t)r[j] * K1 + k);
        #pragma unroll
        for (int kk = 0; kk < 4; kk++) {
            float w[4];
            *(float4*)w = *(const float4*)&Ws[(k + kk) * C + cg * 4];
            #pragma unroll
            for (int j = 0; j < 4; j++)
                #pragma unroll
                for (int c = 0; c < 4; c++)
                    acc[j][c] = fmaf(a[j][kk], w[c], acc[j][c]);
        }
    }
    #pragma unroll
    for (int j = 0; j < 4; j++) {
        int rr = row0 + j;
        if (rr >= NN) break;
        float s = rowscale ? rowscale[rr] : 1.0f;
        float4 o;
        o.x = acc[j][0] * s; o.y = acc[j][1] * s; o.z = acc[j][2] * s; o.w = acc[j][3] * s;
        *(float4*)(out + (size_t)rr * C + cg * 4) = o;
    }
}

// ---------------- gathers (CSR, 8-unroll dual accumulators, fused epilogues) -----------
#define ACC4(acc, v) { acc.x += v.x; acc.y += v.y; acc.z += v.z; acc.w += v.w; }
#define GLOOP8(CSR, SRC, PITCH)                                                    \
    float4 acc = make_float4(0.f, 0.f, 0.f, 0.f);                                  \
    float4 ac2 = make_float4(0.f, 0.f, 0.f, 0.f);                                  \
    int i = s;                                                                     \
    for (; i + 7 < e; i += 8) {                                                    \
        int n0 = CSR[i],     n1 = CSR[i + 1], n2 = CSR[i + 2], n3 = CSR[i + 3];    \
        int n4 = CSR[i + 4], n5 = CSR[i + 5], n6 = CSR[i + 6], n7 = CSR[i + 7];    \
        float4 v0 = *(const float4*)(SRC + (size_t)n0 * PITCH + l * 4);            \
        float4 v1 = *(const float4*)(SRC + (size_t)n1 * PITCH + l * 4);            \
        float4 v2 = *(const float4*)(SRC + (size_t)n2 * PITCH + l * 4);            \
        float4 v3 = *(const float4*)(SRC + (size_t)n3 * PITCH + l * 4);            \
        float4 v4 = *(const float4*)(SRC + (size_t)n4 * PITCH + l * 4);            \
        float4 v5 = *(const float4*)(SRC + (size_t)n5 * PITCH + l * 4);            \
        float4 v6 = *(const float4*)(SRC + (size_t)n6 * PITCH + l * 4);            \
        float4 v7 = *(const float4*)(SRC + (size_t)n7 * PITCH + l * 4);            \
        ACC4(acc, v0); ACC4(ac2, v1); ACC4(acc, v2); ACC4(ac2, v3);                \
        ACC4(acc, v4); ACC4(ac2, v5); ACC4(acc, v6); ACC4(ac2, v7);                \
    }                                                                              \
    for (; i + 3 < e; i += 4) {                                                    \
        int n0 = CSR[i], n1 = CSR[i + 1], n2 = CSR[i + 2], n3 = CSR[i + 3];        \
        float4 v0 = *(const float4*)(SRC + (size_t)n0 * PITCH + l * 4);            \
        float4 v1 = *(const float4*)(SRC + (size_t)n1 * PITCH + l * 4);            \
        float4 v2 = *(const float4*)(SRC + (size_t)n2 * PITCH + l * 4);            \
        float4 v3 = *(const float4*)(SRC + (size_t)n3 * PITCH + l * 4);            \
        ACC4(acc, v0); ACC4(ac2, v1); ACC4(acc, v2); ACC4(ac2, v3);                \
    }                                                                              \
    for (; i < e; i++) {                                                           \
        int n0 = CSR[i];                                                           \
        float4 v0 = *(const float4*)(SRC + (size_t)n0 * PITCH + l * 4);            \
        ACC4(acc, v0);                                                             \
    }                                                                              \
    acc.x += ac2.x; acc.y += ac2.y; acc.z += ac2.z; acc.w += ac2.w;

__global__ void k_gath_he(const float* __restrict__ xw) {
    int t = blockIdx.x * blockDim.x + threadIdx.x;
    int he = t >> 4, l = t & 15;
    if (he >= HEN) return;
    int s = g_offH[he], e = g_offH[he + 1];
    GLOOP8(g_csrHn, xw, D)
    float b = g_Binv[he];
    acc.x *= b; acc.y *= b; acc.z *= b; acc.w *= b;
    *(float4*)(g_ef + (size_t)he * D + l * 4) = acc;
}

__global__ void k_gath_e2n(const float* __restrict__ bias, float* __restrict__ out, int relu) {
    int t = blockIdx.x * blockDim.x + threadIdx.x;
    int node = t >> 4, l = t & 15;
    if (node >= NN) return;
    int s = g_offN[node], e = g_offN[node + 1];
    GLOOP8(g_csrNh, g_ef, D)
    float dv = g_Dninv[node];
    float4 bb = *(const float4*)(bias + l * 4);
    float4 o;
    o.x = dv * acc.x + bb.x; o.y = dv * acc.y + bb.y;
    o.z = dv * acc.z + bb.z; o.w = dv * acc.w + bb.w;
    if (relu) {
        o.x = fmaxf(o.x, 0.f); o.y = fmaxf(o.y, 0.f);
        o.z = fmaxf(o.z, 0.f); o.w = fmaxf(o.w, 0.f);
    }
    *(float4*)(out + (size_t)node * D + l * 4) = o;
}

__global__ void k_gcn64(const float* __restrict__ xwd, const float* __restrict__ bias,
                        float* __restrict__ out) {
    int t = blockIdx.x * blockDim.x + threadIdx.x;
    int node = t >> 4, l = t & 15;
    if (node >= NN) return;
    int s = g_offE[node], e = g_offE[node + 1];
    GLOOP8(g_csrE, xwd, D)
    float4 self = *(const float4*)(xwd + (size_t)node * D + l * 4);
    float ds = g_dis[node];
    float4 bb = *(const float4*)(bias + l * 4);
    float4 o;
    o.x = fmaxf(ds * (acc.x + self.x) + bb.x, 0.f);
    o.y = fmaxf(ds * (acc.y + self.y) + bb.y, 0.f);
    o.z = fmaxf(ds * (acc.z + self.z) + bb.z, 0.f);
    o.w = fmaxf(ds * (acc.w + self.w) + bb.w, 0.f);
    *(float4*)(out + (size_t)node * D + l * 4) = o;
}

// gcn2 gather + folded head: writes FINAL output with bias g_bp
__global__ void k_gcn40(float* __restrict__ out) {
    int t = blockIdx.x * blockDim.x + threadIdx.x;
    int node = t / 10, l = t % 10;
    if (node >= NN) return;
    int s = g_offE[node], e = g_offE[node + 1];
    GLOOP8(g_csrE, g_t40, NC)
    float4 self = *(const float4*)(g_t40 + (size_t)node * NC + l * 4);
    float ds = g_dis[node];
    float4 bb = *(const float4*)(g_bp + l * 4);
    float4 o;
    o.x = ds * (acc.x + self.x) + bb.x;
    o.y = ds * (acc.y + self.y) + bb.y;
    o.z = ds * (acc.z + self.z) + bb.z;
    o.w = ds * (acc.w + self.w) + bb.w;
    *(float4*)(out + (size_t)node * NC + l * 4) = o;
}

// ---------------- launch (single stream) ----------------
extern "C" void kernel_launch(void* const* d_in, const int* in_sizes, int n_in,
                              void* d_out, int out_size) {
    const float* x    = (const float*)d_in[0];
    const void*  eidx = d_in[1];
    const void*  hidx = d_in[2];
    const float* W_h1 = (const float*)d_in[3];
    const float* b_h1 = (const float*)d_in[4];
    const float* W_h2 = (const float*)d_in[5];
    const float* b_h2 = (const float*)d_in[6];
    const float* W_c1 = (const float*)d_in[7];
    const float* b_c1 = (const float*)d_in[8];
    const float* W_c2 = (const float*)d_in[9];
    const float* b_c2 = (const float*)d_in[10];
    const float* W_lp = (const float*)d_in[11];
    const float* b_lp = (const float*)d_in[12];
    float* out = (float*)d_out;

    float *p_xw, *p_h1, *p_h2, *p_xg, *p_t40, *p_dis, *p_Wp;
    cudaGetSymbolAddress((void**)&p_xw,  g_xw);
    cudaGetSymbolAddress((void**)&p_h1,  g_h1);
    cudaGetSymbolAddress((void**)&p_h2,  g_h2);
    cudaGetSymbolAddress((void**)&p_xg,  g_xg);
    cudaGetSymbolAddress((void**)&p_t40, g_t40);
    cudaGetSymbolAddress((void**)&p_dis, g_dis);
    cudaGetSymbolAddress((void**)&p_Wp,  g_Wp);

    const int B = 256;
    const int GR  = (NN + 63) / 64;
    const int GRM = (NN + 127) / 128;

    const int SH128 = 2 * 64 * padw(128 / 2) * 4;
    const int SH64  = 2 * 64 * padw(64 / 2) * 4;
    const int SH192 = 2 * 64 * padw(192 / 2) * 4;
    cudaFuncSetAttribute(k_mma<FIN, 0>, cudaFuncAttributeMaxDynamicSharedMemorySize, SH128);
    cudaFuncSetAttribute(k_mma<D, 0>,   cudaFuncAttributeMaxDynamicSharedMemorySize, SH64);
    cudaFuncSetAttribute(k_mma<FIN, D>, cudaFuncAttributeMaxDynamicSharedMemorySize, SH192);

    // ---- CSR build (+ W-fold riding in scan2f block 3) ----
    k_cnt<<<(EE + B - 1) / B, B>>>(eidx, hidx);
    k_scan1f<<<dim3((NN + 1023) / 1024, 3), 256>>>();
    k_scan2f<<<4, 1024>>>(W_c2, b_c2, W_lp, b_lp);
    k_scan3f<<<dim3((NN + B - 1) / B, 3), B>>>();
    k_fill<<<(EE + B - 1) / B, B>>>(eidx, hidx);

    // ---- hyperconv 1 ----
    k_mma<FIN, 0><<<GRM, 128, SH128>>>(x, nullptr, W_h1, p_xw, nullptr);
    k_gath_he<<<(HEN * 16 + B - 1) / B, B>>>(p_xw);
    k_gath_e2n<<<(NN * 16 + B - 1) / B, B>>>(b_h1, p_h1, 1);

    // ---- hyperconv 2 ----
    k_mma<D, 0><<<GRM, 128, SH64>>>(p_h1, nullptr, W_h2, p_xw, nullptr);
    k_gath_he<<<(HEN * 16 + B - 1) / B, B>>>(p_xw);
    k_gath_e2n<<<(NN * 16 + B - 1) / B, B>>>(b_h2, p_h2, 0);

    // ---- gcn 1 (concat input, dis-prescaled) ----
    k_mma<FIN, D><<<GRM, 128, SH192>>>(x, p_h2, W_c1, p_xw, p_dis);
    k_gcn64<<<(NN * 16 + B - 1) / B, B>>>(p_xw, b_c1, p_xg);

    // ---- gcn 2 with folded linear head (writes final out) ----
    k_gemm<D, NC><<<GR, 160>>>(p_xg, p_Wp, p_t40, p_dis);
    k_gcn40<<<(NN * 10 + 319) / 320, 320>>>(out);
}

// round 13
// speedup vs baseline: 1.4689x; 1.0379x over previous
#include <cuda_runtime.h>
#include <cuda_bf16.h>
#include <cstdint>

#define NN  100000
#define EE  1600000
#define PP  800000
#define HEN 20000
#define FIN 128
#define D   64
#define NC  40

// ---------------- scratch (device globals; no allocation allowed) ----------------
__device__ float g_xw [NN * D];
__device__ float g_h1 [NN * D];
__device__ float g_h2 [NN * D];
__device__ float g_xg [NN * D];
__device__ float g_t40[NN * NC];
__device__ float g_ef [HEN * D];
__device__ float g_dis  [NN];
__device__ float g_Dninv[NN];
__device__ float g_Binv [HEN];
__device__ float g_Wp[D * NC];      // W_c2 @ W_lp
__device__ float g_bp[NC];          // b_c2 @ W_lp + b_lp
__device__ int g_cntE[NN], g_cntH[HEN], g_cntN[NN];   // static zero-init; re-zeroed in fill
__device__ int g_offE[NN + 1], g_offH[HEN + 1], g_offN[NN + 1];
__device__ int g_curE[NN], g_curH[HEN], g_curN[NN];
__device__ int g_csrE[EE];
__device__ int g_csrHn[PP];
__device__ int g_csrNh[PP];
__device__ int g_bsum[512];

// ---------------- helpers ----------------
__device__ __forceinline__ int sniff64(const void* b) {
    int acc = 0;
    #pragma unroll
    for (int i = 0; i < 8; i++) acc |= ((const int*)b)[2 * i + 1];
    return acc == 0;
}
__device__ __forceinline__ long long ldidx(const void* b, long long i, int m64) {
    return m64 ? ((const long long*)b)[i] : (long long)((const int*)b)[i];
}

// ---------------- fused counting ----------------
__global__ void k_cnt(const void* eidx, const void* hidx) {
    int me = sniff64(eidx), mh = sniff64(hidx);
    int i = blockIdx.x * blockDim.x + threadIdx.x;
    if (i < EE) {
        int dst = (int)ldidx(eidx, (long long)EE + i, me);
        atomicAdd(&g_cntE[dst], 1);
    }
    if (i < PP) {
        int node = (int)ldidx(hidx, i, mh);
        int he   = (int)ldidx(hidx, (long long)PP + i, mh);
        atomicAdd(&g_cntN[node], 1);
        atomicAdd(&g_cntH[he], 1);
    }
}

// ---------------- scan stage 1 (y: 0=E,1=N,2=H; y==3: W_lp fold, x==0 only) ----------
__global__ void k_scan1f(const float* __restrict__ W_c2, const float* __restrict__ b_c2,
                         const float* __restrict__ W_lp, const float* __restrict__ b_lp) {
    int t = threadIdx.x;
    if (blockIdx.y == 3) {                      // fold W_lp into W_c2 (free ride)
        if (blockIdx.x != 0) return;
        for (int i = t; i < D * NC + NC; i += 256) {
            if (i < D * NC) {
                int k = i / NC, c = i - k * NC;
                float s = 0.f;
                #pragma unroll
                for (int j = 0; j < NC; j++) s = fmaf(W_c2[k * NC + j], W_lp[j * NC + c], s);
                g_Wp[i] = s;
            } else {
                int c = i - D * NC;
                float s = b_lp[c];
                #pragma unroll
                for (int j = 0; j < NC; j++) s = fmaf(b_c2[j], W_lp[j * NC + c], s);
                g_bp[c] = s;
            }
        }
        return;
    }
    const int* cnt; int n; int* excl; int* bs;
    if (blockIdx.y == 0)      { cnt = g_cntE; n = NN;  excl = g_offE; bs = g_bsum;       }
    else if (blockIdx.y == 1) { cnt = g_cntN; n = NN;  excl = g_offN; bs = g_bsum + 128; }
    else                      { cnt = g_cntH; n = HEN; excl = g_offH; bs = g_bsum + 256; }
    __shared__ int wsum[8];
    int base = blockIdx.x * 1024 + t * 4;
    int v0 = 0, v1 = 0, v2 = 0, v3 = 0;
    if (base + 0 < n) v0 = cnt[base + 0];
    if (base + 1 < n) v1 = cnt[base + 1];
    if (base + 2 < n) v2 = cnt[base + 2];
    if (base + 3 < n) v3 = cnt[base + 3];
    int tot = v0 + v1 + v2 + v3;
    int lane = t & 31, w = t >> 5;
    int p = tot;
    for (int d = 1; d < 32; d <<= 1) { int u = __shfl_up_sync(~0u, p, d); if (lane >= d) p += u; }
    if (lane == 31) wsum[w] = p;
    __syncthreads();
    int wb = 0;
    for (int i = 0; i < w; i++) wb += wsum[i];
    int e0 = wb + p - tot;
    if (base + 0 < n) excl[base + 0] = e0;
    if (base + 1 < n) excl[base + 1] = e0 + v0;
    if (base + 2 < n) excl[base + 2] = e0 + v0 + v1;
    if (base + 3 < n) excl[base + 3] = e0 + v0 + v1 + v2;
    if (t == 255) bs[blockIdx.x] = wb + p;
}

// ---------------- scan stage 2+3 fused: block-base by in-block reduce over bsum ------
// Each block's 256 indices live in ONE 1024-chunk, so the base is sum(bsum[0..chunk)).
__global__ void k_scan3f() {
    __shared__ int sred[256];
    int t = threadIdx.x;
    int y = blockIdx.y;
    int i = blockIdx.x * 256 + t;
    int c = (blockIdx.x * 256) >> 10;                    // chunk, uniform per block
    const int* bs = g_bsum + (y == 0 ? 0 : (y == 1 ? 128 : 256));
    sred[t] = (t < c) ? bs[t] : 0;                       // c <= 98 < 256
    __syncthreads();
    #pragma unroll
    for (int st = 128; st > 0; st >>= 1) {
        if (t < st) sred[t] += sred[t + st];
        __syncthreads();
    }
    int S = sred[0];
    if (y == 0) {
        if (i < NN) {
            int v = g_offE[i] + S;
            g_offE[i] = v; g_curE[i] = v;
            g_dis[i] = rsqrtf((float)g_cntE[i] + 1.0f);
            int dn = g_cntN[i];
            g_Dninv[i] = dn > 0 ? 1.0f / (float)dn : 0.0f;
        }
        if (i < HEN) {
            int bh = g_cntH[i];
            g_Binv[i] = bh > 0 ? 1.0f / (float)bh : 0.0f;
        }
        if (i == 0) g_offE[NN] = EE;
    } else if (y == 1) {
        if (i < NN) {
            int v = g_offN[i] + S;
            g_offN[i] = v; g_curN[i] = v;
        }
        if (i == 0) g_offN[NN] = PP;
    } else {
        if (i < HEN) {
            int v = g_offH[i] + S;
            g_offH[i] = v; g_curH[i] = v;
        }
        if (i == 0) g_offH[HEN] = PP;
    }
}

// ---------------- bf16 split tensor-core GEMM body (C=64) --------------------------
__host__ __device__ constexpr int padw(int v) { int r = v % 32; return v + ((r <= 4) ? (4 - r) : (36 - r)); }

__device__ __forceinline__ void bsplit(float2 q, uint32_t& hi, uint32_t& lo) {
    uint32_t h;
    asm("cvt.rn.bf16x2.f32 %0, %1, %2;" : "=r"(h) : "f"(q.y), "f"(q.x));
    float hx = __uint_as_float(h << 16);
    float hy = __uint_as_float(h & 0xffff0000u);
    float rx = q.x - hx, ry = q.y - hy;
    uint32_t l;
    asm("cvt.rn.bf16x2.f32 %0, %1, %2;" : "=r"(l) : "f"(ry), "f"(rx));
    hi = h; lo = l;
}
#define MMA16816(c, a, b0, b1)                                                     \
    asm volatile("mma.sync.aligned.m16n8k16.row.col.f32.bf16.bf16.f32 "            \
                 "{%0,%1,%2,%3}, {%4,%5,%6,%7}, {%8,%9}, {%0,%1,%2,%3};"           \
                 : "+f"(c[0]), "+f"(c[1]), "+f"(c[2]), "+f"(c[3])                  \
                 : "r"(a[0]), "r"(a[1]), "r"(a[2]), "r"(a[3]), "r"(b0), "r"(b1))

template<int K1, int K2, int WARPS>
__device__ __forceinline__ void gemm_body(
    const float* __restrict__ A1, const float* __restrict__ A2,
    const float* __restrict__ W, float* __restrict__ out,
    const float* __restrict__ rowscale, int bx)
{
    constexpr int KT = K1 + K2;
    constexpr int C = 64;
    constexpr int KPW = padw(KT / 2);
    constexpr int KPE = KPW * 2;
    extern __shared__ unsigned char smraw[];
    __nv_bfloat16* WtHi = (__nv_bfloat16*)smraw;
    __nv_bfloat16* WtLo = WtHi + C * KPE;

    int tid = threadIdx.x;
    for (int idx = tid; idx < KT * C; idx += WARPS * 32) {
        int k = idx >> 6, n = idx & 63;
        float w = W[idx];
        __nv_bfloat16 h = __float2bfloat16(w);
        float lo = w - __bfloat162float(h);
        WtHi[n * KPE + k] = h;
        WtLo[n * KPE + k] = __float2bfloat16(lo);
    }
    __syncthreads();

    const uint32_t* WH = (const uint32_t*)WtHi;
    const uint32_t* WL = (const uint32_t*)WtLo;

    int w = tid >> 5, lane = tid & 31;
    int g = lane >> 2, t = lane & 3;
    int m0 = bx * (WARPS * 32) + w * 32;
    int rows[4] = { m0 + g, m0 + g + 8, m0 + 16 + g, m0 + 24 + g };
    int rc[4];
    #pragma unroll
    for (int i = 0; i < 4; i++) rc[i] = rows[i] < NN ? rows[i] : NN - 1;

    float acc[2][8][4] = {};

    for (int kc = 0; kc < KT / 16; kc++) {
        int kk = kc * 16;
        uint32_t ah[2][4], al[2][4];
        #pragma unroll
        for (int f = 0; f < 2; f++) {
            const float *p0, *p1;
            if (K2 == 0 || kk < K1) {
                p0 = A1 + (size_t)rc[2 * f] * K1 + kk;
                p1 = A1 + (size_t)rc[2 * f + 1] * K1 + kk;
            } else {
                p0 = A2 + (size_t)rc[2 * f] * K2 + (kk - K1);
                p1 = A2 + (size_t)rc[2 * f + 1] * K2 + (kk - K1);
            }
            float2 q0 = *(const float2*)(p0 + 2 * t);
            float2 q1 = *(const float2*)(p1 + 2 * t);
            float2 q2 = *(const float2*)(p0 + 2 * t + 8);
            float2 q3 = *(const float2*)(p1 + 2 * t + 8);
            bsplit(q0, ah[f][0], al[f][0]);
            bsplit(q1, ah[f][1], al[f][1]);
            bsplit(q2, ah[f][2], al[f][2]);
            bsplit(q3, ah[f][3], al[f][3]);
        }
        #pragma unroll
        for (int s = 0; s < 8; s++) {
            int wi = (s * 8 + g) * KPW + kc * 8 + t;
            uint32_t bh0 = WH[wi], bh1 = WH[wi + 4];
            uint32_t bl0 = WL[wi], bl1 = WL[wi + 4];
            #pragma unroll
            for (int f = 0; f < 2; f++) {
                MMA16816(acc[f][s], ah[f], bh0, bh1);
                MMA16816(acc[f][s], al[f], bh0, bh1);
                MMA16816(acc[f][s], ah[f], bl0, bl1);
            }
        }
    }

    float rs[4] = {1.f, 1.f, 1.f, 1.f};
    if (rowscale) {
        #pragma unroll
        for (int i = 0; i < 4; i++) rs[i] = rowscale[rc[i]];
    }
    #pragma unroll
    for (int f = 0; f < 2; f++) {
        #pragma unroll
        for (int s = 0; s < 8; s++) {
            int col = s * 8 + 2 * t;
            int ra = rows[2 * f], rb = rows[2 * f + 1];
            if (ra < NN) {
                float2 v = { acc[f][s][0] * rs[2 * f], acc[f][s][1] * rs[2 * f] };
                *(float2*)(out + (size_t)ra * 64 + col) = v;
            }
            if (rb < NN) {
                float2 v = { acc[f][s][2] * rs[2 * f + 1], acc[f][s][3] * rs[2 * f + 1] };
                *(float2*)(out + (size_t)rb * 64 + col) = v;
            }
        }
    }
}

template<int K1, int K2>
__global__ void k_mma(const float* __restrict__ A1, const float* __restrict__ A2,
                      const float* __restrict__ W, float* __restrict__ out,
                      const float* __restrict__ rowscale) {
    gemm_body<K1, K2, 4>(A1, A2, W, out, rowscale, blockIdx.x);
}

// ---------------- fused: CSR fill + GEMM1 (x@W_h1) in one launch -------------------
#define GEMM_BLKS ((NN + 255) / 256)    // 391, 8 warps x 32 rows each
__global__ void k_fill_gemm(const void* eidx, const void* hidx,
                            const float* __restrict__ x, const float* __restrict__ W,
                            float* __restrict__ xw) {
    if (blockIdx.x < GEMM_BLKS) {
        gemm_body<FIN, 0, 8>(x, nullptr, W, xw, nullptr, blockIdx.x);
        return;
    }
    int bid = blockIdx.x - GEMM_BLKS;
    int me = sniff64(eidx), mh = sniff64(hidx);
    int i = bid * blockDim.x + threadIdx.x;
    if (i < EE) {
        int src = (int)ldidx(eidx, i, me);
        int dst = (int)ldidx(eidx, (long long)EE + i, me);
        int pos = atomicAdd(&g_curE[dst], 1);
        g_csrE[pos] = src;
    }
    if (i < PP) {
        int node = (int)ldidx(hidx, i, mh);
        int he   = (int)ldidx(hidx, (long long)PP + i, mh);
        int p1 = atomicAdd(&g_curH[he], 1);   g_csrHn[p1] = node;
        int p2 = atomicAdd(&g_curN[node], 1); g_csrNh[p2] = he;
    }
    if (i < NN) { g_cntE[i] = 0; g_cntN[i] = 0; }   // restore zero invariant for replay
    if (i < HEN) g_cntH[i] = 0;
}

// ---------------- FFMA GEMM (C=40, W from device global): out = rowscale*(A@W) ------
template<int K1, int C>
__global__ void k_gemm(const float* __restrict__ A1, const float* __restrict__ W,
                       float* __restrict__ out, const float* __restrict__ rowscale) {
    constexpr int CG = C / 4;
    __shared__ float Ws[K1 * C];
    int tid = threadIdx.x;
    for (int i = tid; i < K1 * C; i += CG * 16) Ws[i] = W[i];
    __syncthreads();
    int cg = tid % CG, rg = tid / CG;
    int row0 = blockIdx.x * 64 + rg * 4;
    int r[4];
    #pragma unroll
    for (int j = 0; j < 4; j++) { int rr = row0 + j; r[j] = rr < NN ? rr : NN - 1; }

    float acc[4][4] = {};
    #pragma unroll 2
    for (int k = 0; k < K1; k += 4) {
        float a[4][4];
        #pragma unroll
        for (int j = 0; j < 4; j++)
            *(float4*)a[j] = *(const float4*)(A1 + (size_t)r[j] * K1 + k);
        #pragma unroll
        for (int kk = 0; kk < 4; kk++) {
            float w[4];
            *(float4*)w = *(const float4*)&Ws[(k + kk) * C + cg * 4];
            #pragma unroll
            for (int j = 0; j < 4; j++)
                #pragma unroll
                for (int c = 0; c < 4; c++)
                    acc[j][c] = fmaf(a[j][kk], w[c], acc[j][c]);
        }
    }
    #pragma unroll
    for (int j = 0; j < 4; j++) {
        int rr = row0 + j;
        if (rr >= NN) break;
        float s = rowscale ? rowscale[rr] : 1.0f;
        float4 o;
        o.x = acc[j][0] * s; o.y = acc[j][1] * s; o.z = acc[j][2] * s; o.w = acc[j][3] * s;
        *(float4*)(out + (size_t)rr * C + cg * 4) = o;
    }
}

// ---------------- gathers (CSR, 8-unroll dual accumulators, fused epilogues) ---------
#define ACC4(acc, v) { acc.x += v.x; acc.y += v.y; acc.z += v.z; acc.w += v.w; }
#define GLOOP8(CSR, SRC, PITCH)                                                    \
    float4 acc = make_float4(0.f, 0.f, 0.f, 0.f);                                  \
    float4 ac2 = make_float4(0.f, 0.f, 0.f, 0.f);                                  \
    int i = s;                                                                     \
    for (; i + 7 < e; i += 8) {                                                    \
        int n0 = CSR[i],     n1 = CSR[i + 1], n2 = CSR[i + 2], n3 = CSR[i + 3];    \
        int n4 = CSR[i + 4], n5 = CSR[i + 5], n6 = CSR[i + 6], n7 = CSR[i + 7];    \
        float4 v0 = *(const float4*)(SRC + (size_t)n0 * PITCH + l * 4);            \
        float4 v1 = *(const float4*)(SRC + (size_t)n1 * PITCH + l * 4);            \
        float4 v2 = *(const float4*)(SRC + (size_t)n2 * PITCH + l * 4);            \
        float4 v3 = *(const float4*)(SRC + (size_t)n3 * PITCH + l * 4);            \
        float4 v4 = *(const float4*)(SRC + (size_t)n4 * PITCH + l * 4);            \
        float4 v5 = *(const float4*)(SRC + (size_t)n5 * PITCH + l * 4);            \
        float4 v6 = *(const float4*)(SRC + (size_t)n6 * PITCH + l * 4);            \
        float4 v7 = *(const float4*)(SRC + (size_t)n7 * PITCH + l * 4);            \
        ACC4(acc, v0); ACC4(ac2, v1); ACC4(acc, v2); ACC4(ac2, v3);                \
        ACC4(acc, v4); ACC4(ac2, v5); ACC4(acc, v6); ACC4(ac2, v7);                \
    }                                                                              \
    for (; i + 3 < e; i += 4) {                                                    \
        int n0 = CSR[i], n1 = CSR[i + 1], n2 = CSR[i + 2], n3 = CSR[i + 3];        \
        float4 v0 = *(const float4*)(SRC + (size_t)n0 * PITCH + l * 4);            \
        float4 v1 = *(const float4*)(SRC + (size_t)n1 * PITCH + l * 4);            \
        float4 v2 = *(const float4*)(SRC + (size_t)n2 * PITCH + l * 4);            \
        float4 v3 = *(const float4*)(SRC + (size_t)n3 * PITCH + l * 4);            \
        ACC4(acc, v0); ACC4(ac2, v1); ACC4(acc, v2); ACC4(ac2, v3);                \
    }                                                                              \
    for (; i < e; i++) {                                                           \
        int n0 = CSR[i];                                                           \
        float4 v0 = *(const float4*)(SRC + (size_t)n0 * PITCH + l * 4);            \
        ACC4(acc, v0);                                                             \
    }                                                                              \
    acc.x += ac2.x; acc.y += ac2.y; acc.z += ac2.z; acc.w += ac2.w;

__global__ void k_gath_he(const float* __restrict__ xw) {
    int t = blockIdx.x * blockDim.x + threadIdx.x;
    int he = t >> 4, l = t & 15;
    if (he >= HEN) return;
    int s = g_offH[he], e = g_offH[he + 1];
    GLOOP8(g_csrHn, xw, D)
    float b = g_Binv[he];
    acc.x *= b; acc.y *= b; acc.z *= b; acc.w *= b;
    *(float4*)(g_ef + (size_t)he * D + l * 4) = acc;
}

__global__ void k_gath_e2n(const float* __restrict__ bias, float* __restrict__ out, int relu) {
    int t = blockIdx.x * blockDim.x + threadIdx.x;
    int node = t >> 4, l = t & 15;
    if (node >= NN) return;
    int s = g_offN[node], e = g_offN[node + 1];
    GLOOP8(g_csrNh, g_ef, D)
    float dv = g_Dninv[node];
    float4 bb = *(const float4*)(bias + l * 4);
    float4 o;
    o.x = dv * acc.x + bb.x; o.y = dv * acc.y + bb.y;
    o.z = dv * acc.z + bb.z; o.w = dv * acc.w + bb.w;
    if (relu) {
        o.x = fmaxf(o.x, 0.f); o.y = fmaxf(o.y, 0.f);
        o.z = fmaxf(o.z, 0.f); o.w = fmaxf(o.w, 0.f);
    }
    *(float4*)(out + (size_t)node * D + l * 4) = o;
}

__global__ void k_gcn64(const float* __restrict__ xwd, const float* __restrict__ bias,
                        float* __restrict__ out) {
    int t = blockIdx.x * blockDim.x + threadIdx.x;
    int node = t >> 4, l = t & 15;
    if (node >= NN) return;
    int s = g_offE[node], e = g_offE[node + 1];
    GLOOP8(g_csrE, xwd, D)
    float4 self = *(const float4*)(xwd + (size_t)node * D + l * 4);
    float ds = g_dis[node];
    float4 bb = *(const float4*)(bias + l * 4);
    float4 o;
    o.x = fmaxf(ds * (acc.x + self.x) + bb.x, 0.f);
    o.y = fmaxf(ds * (acc.y + self.y) + bb.y, 0.f);
    o.z = fmaxf(ds * (acc.z + self.z) + bb.z, 0.f);
    o.w = fmaxf(ds * (acc.w + self.w) + bb.w, 0.f);
    *(float4*)(out + (size_t)node * D + l * 4) = o;
}

// gcn2 gather + folded head: writes FINAL output with bias g_bp
__global__ void k_gcn40(float* __restrict__ out) {
    int t = blockIdx.x * blockDim.x + threadIdx.x;
    int node = t / 10, l = t % 10;
    if (node >= NN) return;
    int s = g_offE[node], e = g_offE[node + 1];
    GLOOP8(g_csrE, g_t40, NC)
    float4 self = *(const float4*)(g_t40 + (size_t)node * NC + l * 4);
    float ds = g_dis[node];
    float4 bb = *(const float4*)(g_bp + l * 4);
    float4 o;
    o.x = ds * (acc.x + self.x) + bb.x;
    o.y = ds * (acc.y + self.y) + bb.y;
    o.z = ds * (acc.z + self.z) + bb.z;
    o.w = ds * (acc.w + self.w) + bb.w;
    *(float4*)(out + (size_t)node * NC + l * 4) = o;
}

// ---------------- launch (single stream) ----------------
extern "C" void kernel_launch(void* const* d_in, const int* in_sizes, int n_in,
                              void* d_out, int out_size) {
    const float* x    = (const float*)d_in[0];
    const void*  eidx = d_in[1];
    const void*  hidx = d_in[2];
    const float* W_h1 = (const float*)d_in[3];
    const float* b_h1 = (const float*)d_in[4];
    const float* W_h2 = (const float*)d_in[5];
    const float* b_h2 = (const float*)d_in[6];
    const float* W_c1 = (const float*)d_in[7];
    const float* b_c1 = (const float*)d_in[8];
    const float* W_c2 = (const float*)d_in[9];
    const float* b_c2 = (const float*)d_in[10];
    const float* W_lp = (const float*)d_in[11];
    const float* b_lp = (const float*)d_in[12];
    float* out = (float*)d_out;

    float *p_xw, *p_h1, *p_h2, *p_xg, *p_t40, *p_dis, *p_Wp;
    cudaGetSymbolAddress((void**)&p_xw,  g_xw);
    cudaGetSymbolAddress((void**)&p_h1,  g_h1);
    cudaGetSymbolAddress((void**)&p_h2,  g_h2);
    cudaGetSymbolAddress((void**)&p_xg,  g_xg);
    cudaGetSymbolAddress((void**)&p_t40, g_t40);
    cudaGetSymbolAddress((void**)&p_dis, g_dis);
    cudaGetSymbolAddress((void**)&p_Wp,  g_Wp);

    const int B = 256;
    const int GR  = (NN + 63) / 64;
    const int GRM = (NN + 127) / 128;

    const int SH128 = 2 * 64 * padw(128 / 2) * 4;   // 34816
    const int SH64  = 2 * 64 * padw(64 / 2) * 4;    // 18432
    const int SH192 = 2 * 64 * padw(192 / 2) * 4;   // 51200 (>48KB)
    cudaFuncSetAttribute(k_mma<D, 0>,   cudaFuncAttributeMaxDynamicSharedMemorySize, SH64);
    cudaFuncSetAttribute(k_mma<FIN, D>, cudaFuncAttributeMaxDynamicSharedMemorySize, SH192);
    cudaFuncSetAttribute(k_fill_gemm,   cudaFuncAttributeMaxDynamicSharedMemorySize, SH128);

    // ---- CSR build (scan2 eliminated; GEMM1 fused into fill) ----
    k_cnt<<<(EE + B - 1) / B, B>>>(eidx, hidx);
    k_scan1f<<<dim3((NN + 1023) / 1024, 4), 256>>>(W_c2, b_c2, W_lp, b_lp);
    k_scan3f<<<dim3((NN + 255) / 256, 3), 256>>>();
    k_fill_gemm<<<GEMM_BLKS + (EE + B - 1) / B, B, SH128>>>(eidx, hidx, x, W_h1, p_xw);

    // ---- hyperconv 1 (gemm already done in fused launch) ----
    k_gath_he<<<(HEN * 16 + B - 1) / B, B>>>(p_xw);
    k_gath_e2n<<<(NN * 16 + B - 1) / B, B>>>(b_h1, p_h1, 1);

    // ---- hyperconv 2 ----
    k_mma<D, 0><<<GRM, 128, SH64>>>(p_h1, nullptr, W_h2, p_xw, nullptr);
    k_gath_he<<<(HEN * 16 + B - 1) / B, B>>>(p_xw);
    k_gath_e2n<<<(NN * 16 + B - 1) / B, B>>>(b_h2, p_h2, 0);

    // ---- gcn 1 (concat input, dis-prescaled) ----
    k_mma<FIN, D><<<GRM, 128, SH192>>>(x, p_h2, W_c1, p_xw, p_dis);
    k_gcn64<<<(NN * 16 + B - 1) / B, B>>>(p_xw, b_c1, p_xg);

    // ---- gcn 2 with folded linear head (writes final out) ----
    k_gemm<D, NC><<<GR, 160>>>(p_xg, p_Wp, p_t40, p_dis);
    k_gcn40<<<(NN * 10 + 319) / 320, 320>>>(out);
}